// round 2
// baseline (speedup 1.0000x reference)
#include <cuda_runtime.h>
#include <cuda_fp16.h>
#include <cstdint>

#define NROW 200000
#define XDIM 480
#define ROWS 64
#define NTILES (NROW / ROWS)   // 3125 exactly
#define GRID 152

#define DINL __device__ __forceinline__

DINL unsigned su32(const void* p){ return (unsigned)__cvta_generic_to_shared(p); }

DINL void ldmx4(unsigned &r0,unsigned &r1,unsigned &r2,unsigned &r3, unsigned a){
  asm volatile("ldmatrix.sync.aligned.m8n8.x4.shared.b16 {%0,%1,%2,%3}, [%4];"
    : "=r"(r0),"=r"(r1),"=r"(r2),"=r"(r3) : "r"(a));
}
DINL void ldmx4t(unsigned &r0,unsigned &r1,unsigned &r2,unsigned &r3, unsigned a){
  asm volatile("ldmatrix.sync.aligned.m8n8.x4.trans.shared.b16 {%0,%1,%2,%3}, [%4];"
    : "=r"(r0),"=r"(r1),"=r"(r2),"=r"(r3) : "r"(a));
}
DINL void mma16816(float* c, unsigned a0,unsigned a1,unsigned a2,unsigned a3,
                   unsigned b0,unsigned b1){
  asm volatile("mma.sync.aligned.m16n8k16.row.col.f32.f16.f16.f32 "
    "{%0,%1,%2,%3}, {%4,%5,%6,%7}, {%8,%9}, {%0,%1,%2,%3};"
    : "+f"(c[0]),"+f"(c[1]),"+f"(c[2]),"+f"(c[3])
    : "r"(a0),"r"(a1),"r"(a2),"r"(a3),"r"(b0),"r"(b1));
}
DINL float sigm(float v){ return 1.f/(1.f+__expf(-v)); }

// A-operand ldmatrix address: 16x16 tile at (r0, k0) of row-major [.,stride] half matrix
DINL unsigned aaddr(unsigned base, int stride, int r0, int k0, int lane){
  int r = r0 + (lane & 15);
  int c = k0 + ((lane >> 4) << 3);
  return base + (unsigned)((r * stride + c) << 1);
}
// B-operand x4.trans address: covers k-tile [k0,k0+16) x n cols [c0,c0+16) of row-major [K][N]
DINL unsigned baddr(unsigned base, int stride, int k0, int c0, int lane){
  int r = k0 + (lane & 7) + (((lane >> 3) & 1) << 3);
  int c = c0 + ((lane >> 4) << 3);
  return base + (unsigned)((r * stride + c) << 1);
}

// fp16 weights with 1/sqrt(fan_in) folded
__device__ __half WP0[128*256];
__device__ __half WQ0[256*128];
__device__ __half WP1[64*128];
__device__ __half WQ1[128*64];
__device__ __half WP2[32*64];
__device__ __half WQ2[64*32];

__global__ void k_prep(const float* __restrict__ p0, const float* __restrict__ p1,
                       const float* __restrict__ p2, const float* __restrict__ q0,
                       const float* __restrict__ q1, const float* __restrict__ q2){
  int t = blockIdx.x*blockDim.x + threadIdx.x, st = gridDim.x*blockDim.x;
  for (int i=t;i<128*256;i+=st) WP0[i] = __float2half(p0[i]*0.08838834764831845f); // 1/sqrt(128)
  for (int i=t;i<64*128;i+=st)  WP1[i] = __float2half(p1[i]*0.125f);               // 1/sqrt(64)
  for (int i=t;i<32*64;i+=st)   WP2[i] = __float2half(p2[i]*0.17677669529663687f); // 1/sqrt(32)
  for (int i=t;i<256*128;i+=st) WQ0[i] = __float2half(q0[i]*0.0625f);              // 1/sqrt(256)
  for (int i=t;i<128*64;i+=st)  WQ1[i] = __float2half(q1[i]*0.08838834764831845f);
  for (int i=t;i<64*32;i+=st)   WQ2[i] = __float2half(q2[i]*0.125f);
}

// ============================ l = 0 ============================
struct SL0 {
  float  xs[64][132];      // raw x slice (fp32) for residual
  float  nw[128], nb[128];
  __half wp[128][264];
  __half wq[256][136];
  __half A[64][136];       // normalized activations
  __half H[64][264];       // hidden (post-sigmoid); reused as float[64][132] out buffer
};

__global__ __launch_bounds__(512,1) void k_l0(const float* __restrict__ x,
                                              float* __restrict__ out,
                                              const float* __restrict__ w0,
                                              const float* __restrict__ b0){
  extern __shared__ __align__(16) char smem[];
  SL0& s = *reinterpret_cast<SL0*>(smem);
  const int tid = threadIdx.x, lane = tid & 31, warp = tid >> 5;

  for (int i=tid;i<128*256;i+=512) s.wp[i>>8][i&255] = WP0[i];
  for (int i=tid;i<256*128;i+=512) s.wq[i>>7][i&127] = WQ0[i];
  if (tid < 128){ s.nw[tid] = w0[tid]; s.nb[tid] = b0[tid]; }
  __syncthreads();

  const unsigned aB = su32(&s.A[0][0]);
  const unsigned hB = su32(&s.H[0][0]);
  const unsigned pB = su32(&s.wp[0][0]);
  const unsigned qB = su32(&s.wq[0][0]);

  const int r0  = (warp >> 2) << 4;  // 0..48
  const int c0  = (warp & 3) << 6;   // GEMM1 cols (64 wide)
  const int c0b = (warp & 3) << 5;   // GEMM2 cols (32 wide)

  for (int tile = blockIdx.x; tile < NTILES; tile += gridDim.x){
    const int n0 = tile * ROWS;
    { // ---- load + layernorm ----
      const int row = tid >> 3, sub = tid & 7;
      const float4* xr = reinterpret_cast<const float4*>(x + (size_t)(n0+row)*XDIM + sub*16);
      float4 v0 = xr[0], v1 = xr[1], v2 = xr[2], v3 = xr[3];
      float vv[16] = {v0.x,v0.y,v0.z,v0.w, v1.x,v1.y,v1.z,v1.w,
                      v2.x,v2.y,v2.z,v2.w, v3.x,v3.y,v3.z,v3.w};
      float sm = 0.f, sq = 0.f;
      #pragma unroll
      for (int j=0;j<16;j++){ sm += vv[j]; sq += vv[j]*vv[j]; }
      #pragma unroll
      for (int o=1;o<8;o<<=1){ sm += __shfl_xor_sync(~0u, sm, o); sq += __shfl_xor_sync(~0u, sq, o); }
      float mu = sm * (1.f/128.f);
      float rinv = rsqrtf(sq*(1.f/128.f) - mu*mu + 1e-5f);
      float4* xd = reinterpret_cast<float4*>(&s.xs[row][sub*16]);
      xd[0]=v0; xd[1]=v1; xd[2]=v2; xd[3]=v3;
      const int cb = sub*16;
      __half2* ad = reinterpret_cast<__half2*>(&s.A[row][cb]);
      #pragma unroll
      for (int j=0;j<8;j++){
        float a0f = (vv[2*j]   - mu)*rinv*s.nw[cb+2*j]   + s.nb[cb+2*j];
        float a1f = (vv[2*j+1] - mu)*rinv*s.nw[cb+2*j+1] + s.nb[cb+2*j+1];
        ad[j] = __floats2half2_rn(a0f, a1f);
      }
    }
    __syncthreads();
    { // ---- GEMM1 + sigmoid -> H ----
      float acc[8][4];
      #pragma unroll
      for (int j=0;j<8;j++){ acc[j][0]=acc[j][1]=acc[j][2]=acc[j][3]=0.f; }
      #pragma unroll
      for (int k=0;k<8;k++){
        unsigned a0,a1,a2,a3;
        ldmx4(a0,a1,a2,a3, aaddr(aB,136,r0,k*16,lane));
        #pragma unroll
        for (int j=0;j<4;j++){
          unsigned b0,b1,b2,b3;
          ldmx4t(b0,b1,b2,b3, baddr(pB,264,k*16,c0+j*16,lane));
          mma16816(acc[2*j],   a0,a1,a2,a3, b0,b1);
          mma16816(acc[2*j+1], a0,a1,a2,a3, b2,b3);
        }
      }
      const int rr = r0 + (lane>>2), cc = c0 + ((lane&3)<<1);
      #pragma unroll
      for (int j=0;j<8;j++){
        *reinterpret_cast<__half2*>(&s.H[rr  ][cc+8*j]) = __floats2half2_rn(sigm(acc[j][0]), sigm(acc[j][1]));
        *reinterpret_cast<__half2*>(&s.H[rr+8][cc+8*j]) = __floats2half2_rn(sigm(acc[j][2]), sigm(acc[j][3]));
      }
    }
    __syncthreads();
    // ---- GEMM2 ----
    float acc2[4][4];
    #pragma unroll
    for (int j=0;j<4;j++){ acc2[j][0]=acc2[j][1]=acc2[j][2]=acc2[j][3]=0.f; }
    #pragma unroll
    for (int k=0;k<16;k++){
      unsigned a0,a1,a2,a3;
      ldmx4(a0,a1,a2,a3, aaddr(hB,264,r0,k*16,lane));
      #pragma unroll
      for (int j=0;j<2;j++){
        unsigned b0,b1,b2,b3;
        ldmx4t(b0,b1,b2,b3, baddr(qB,136,k*16,c0b+j*16,lane));
        mma16816(acc2[2*j],   a0,a1,a2,a3, b0,b1);
        mma16816(acc2[2*j+1], a0,a1,a2,a3, b2,b3);
      }
    }
    __syncthreads();   // everyone done reading H
    { // ---- residual into ob (reuse H) ----
      float* ob = reinterpret_cast<float*>(&s.H[0][0]);
      const int rr = r0 + (lane>>2), cc = c0b + ((lane&3)<<1);
      #pragma unroll
      for (int j=0;j<4;j++){
        int c = cc + 8*j;
        ob[rr*132 + c]       = acc2[j][0] + s.xs[rr][c];
        ob[rr*132 + c + 1]   = acc2[j][1] + s.xs[rr][c+1];
        ob[(rr+8)*132 + c]   = acc2[j][2] + s.xs[rr+8][c];
        ob[(rr+8)*132 + c+1] = acc2[j][3] + s.xs[rr+8][c+1];
      }
    }
    __syncthreads();
    { // ---- coalesced store ----
      const float* ob = reinterpret_cast<const float*>(&s.H[0][0]);
      #pragma unroll
      for (int i=0;i<4;i++){
        int idx = tid + i*512;          // 64 rows * 32 float4
        int row = idx >> 5, q = idx & 31;
        float4 v = *reinterpret_cast<const float4*>(&ob[row*132 + q*4]);
        *reinterpret_cast<float4*>(out + (size_t)(n0+row)*XDIM + q*4) = v;
      }
    }
    __syncthreads();
  }
}

// ============================ l = 1 ============================
struct SL1 {
  float  xs[64][196];
  float  nw[64];
  __half wp[64][136];
  __half wq[128][72];
  __half A[192][72];
  __half H[192][136];   // reused as float[64][196] out buffer
};

__global__ __launch_bounds__(512,1) void k_l1(const float* __restrict__ x,
                                              float* __restrict__ out,
                                              const float* __restrict__ w1){
  extern __shared__ __align__(16) char smem[];
  SL1& s = *reinterpret_cast<SL1*>(smem);
  const int tid = threadIdx.x, lane = tid & 31, warp = tid >> 5;

  for (int i=tid;i<64*128;i+=512) s.wp[i>>7][i&127] = WP1[i];
  for (int i=tid;i<128*64;i+=512) s.wq[i>>6][i&63]  = WQ1[i];
  if (tid < 64) s.nw[tid] = w1[tid];
  __syncthreads();

  const unsigned aB = su32(&s.A[0][0]);
  const unsigned hB = su32(&s.H[0][0]);
  const unsigned pB = su32(&s.wp[0][0]);
  const unsigned qB = su32(&s.wq[0][0]);

  for (int tile = blockIdx.x; tile < NTILES; tile += gridDim.x){
    const int n0 = tile * ROWS;
    { // ---- load + RMS norm; scatter into (n*3+m, c) layout ----
      const int row = tid >> 3, sub = tid & 7;
      const float4* xr = reinterpret_cast<const float4*>(x + (size_t)(n0+row)*XDIM + 128 + sub*24);
      float4 w[6];
      #pragma unroll
      for (int j=0;j<6;j++) w[j] = xr[j];
      float vv[24] = {w[0].x,w[0].y,w[0].z,w[0].w, w[1].x,w[1].y,w[1].z,w[1].w,
                      w[2].x,w[2].y,w[2].z,w[2].w, w[3].x,w[3].y,w[3].z,w[3].w,
                      w[4].x,w[4].y,w[4].z,w[4].w, w[5].x,w[5].y,w[5].z,w[5].w};
      float sq = 0.f;
      #pragma unroll
      for (int j=0;j<24;j++) sq += vv[j]*vv[j];
      #pragma unroll
      for (int o=1;o<8;o<<=1) sq += __shfl_xor_sync(~0u, sq, o);
      float rinv = rsqrtf(sq*(1.f/64.f) + 1e-5f);
      float4* xd = reinterpret_cast<float4*>(&s.xs[row][sub*24]);
      #pragma unroll
      for (int j=0;j<6;j++) xd[j] = w[j];
      #pragma unroll
      for (int j=0;j<24;j++){
        int c = sub*8 + j/3, m = j - 3*(j/3);
        s.A[row*3 + m][c] = __float2half(vv[j]*rinv*s.nw[c]);
      }
    }
    __syncthreads();
    // ---- GEMM1: H(raw) = A[192x64] @ wp[64x128]; 48 tiles of 16x32 ----
    #pragma unroll
    for (int tt=0;tt<3;tt++){
      const int ti = warp + 16*tt;
      const int r0 = (ti>>2)<<4, c0 = (ti&3)<<5;
      float acc[4][4];
      #pragma unroll
      for (int j=0;j<4;j++){ acc[j][0]=acc[j][1]=acc[j][2]=acc[j][3]=0.f; }
      #pragma unroll
      for (int k=0;k<4;k++){
        unsigned a0,a1,a2,a3;
        ldmx4(a0,a1,a2,a3, aaddr(aB,72,r0,k*16,lane));
        #pragma unroll
        for (int j=0;j<2;j++){
          unsigned b0,b1,b2,b3;
          ldmx4t(b0,b1,b2,b3, baddr(pB,136,k*16,c0+j*16,lane));
          mma16816(acc[2*j],   a0,a1,a2,a3, b0,b1);
          mma16816(acc[2*j+1], a0,a1,a2,a3, b2,b3);
        }
      }
      const int rr = r0 + (lane>>2), cc = c0 + ((lane&3)<<1);
      #pragma unroll
      for (int j=0;j<4;j++){
        *reinterpret_cast<__half2*>(&s.H[rr  ][cc+8*j]) = __floats2half2_rn(acc[j][0], acc[j][1]);
        *reinterpret_cast<__half2*>(&s.H[rr+8][cc+8*j]) = __floats2half2_rn(acc[j][2], acc[j][3]);
      }
    }
    __syncthreads();
    // ---- gate: per (n,o) across 3 m's ----
    #pragma unroll
    for (int it=0; it<16; it++){
      int i = tid + it*512;            // 64*128 elems
      int n = i >> 7, o = i & 127;
      float h0 = __half2float(s.H[3*n  ][o]);
      float h1 = __half2float(s.H[3*n+1][o]);
      float h2 = __half2float(s.H[3*n+2][o]);
      float g = sigm(sqrtf(h0*h0 + h1*h1 + h2*h2 + 1e-12f));
      s.H[3*n  ][o] = __float2half(h0*g);
      s.H[3*n+1][o] = __float2half(h1*g);
      s.H[3*n+2][o] = __float2half(h2*g);
    }
    __syncthreads();
    // ---- GEMM2: Y = H[192x128] @ wq[128x64]; 48 tiles of 16x16 ----
    float acc2[3][2][4];
    #pragma unroll
    for (int tt=0;tt<3;tt++)
      #pragma unroll
      for (int j=0;j<2;j++){ acc2[tt][j][0]=acc2[tt][j][1]=acc2[tt][j][2]=acc2[tt][j][3]=0.f; }
    #pragma unroll
    for (int tt=0;tt<3;tt++){
      const int ti = warp + 16*tt;
      const int r0 = (ti>>2)<<4, c0 = (ti&3)<<4;
      #pragma unroll
      for (int k=0;k<8;k++){
        unsigned a0,a1,a2,a3;
        ldmx4(a0,a1,a2,a3, aaddr(hB,136,r0,k*16,lane));
        unsigned b0,b1,b2,b3;
        ldmx4t(b0,b1,b2,b3, baddr(qB,72,k*16,c0,lane));
        mma16816(acc2[tt][0], a0,a1,a2,a3, b0,b1);
        mma16816(acc2[tt][1], a0,a1,a2,a3, b2,b3);
      }
    }
    __syncthreads();   // H reads done
    { // ---- residual, re-layout (n*3+m, c) -> (n, c*3+m) in ob (reuse H) ----
      float* ob = reinterpret_cast<float*>(&s.H[0][0]);
      #pragma unroll
      for (int tt=0;tt<3;tt++){
        const int ti = warp + 16*tt;
        const int r0 = (ti>>2)<<4, c0 = (ti&3)<<4;
        const int rr = r0 + (lane>>2), cc = c0 + ((lane&3)<<1);
        #pragma unroll
        for (int j=0;j<2;j++){
          int c = cc + 8*j;
          #pragma unroll
          for (int h=0;h<2;h++){
            int r = rr + 8*h;
            int n = r/3, m = r - 3*(r/3);
            ob[n*196 + c*3 + m]     = acc2[tt][j][2*h]   + s.xs[n][c*3 + m];
            ob[n*196 + (c+1)*3 + m] = acc2[tt][j][2*h+1] + s.xs[n][(c+1)*3 + m];
          }
        }
      }
    }
    __syncthreads();
    { // ---- coalesced store ----
      const float* ob = reinterpret_cast<const float*>(&s.H[0][0]);
      #pragma unroll
      for (int i=0;i<6;i++){
        int idx = tid + i*512;          // 64 rows * 48 float4
        int row = idx/48, q = idx - 48*row;
        float4 v = *reinterpret_cast<const float4*>(&ob[row*196 + q*4]);
        *reinterpret_cast<float4*>(out + (size_t)(n0+row)*XDIM + 128 + q*4) = v;
      }
    }
    __syncthreads();
  }
}

// ============================ l = 2 ============================
struct SL2 {
  float  xs[64][164];
  float  nw[32];
  __half wp[32][72];
  __half wq[64][40];
  __half A[320][40];
  __half H[320][72];    // reused as float[64][164] out buffer
};

__global__ __launch_bounds__(512,1) void k_l2(const float* __restrict__ x,
                                              float* __restrict__ out,
                                              const float* __restrict__ w2){
  extern __shared__ __align__(16) char smem[];
  SL2& s = *reinterpret_cast<SL2*>(smem);
  const int tid = threadIdx.x, lane = tid & 31, warp = tid >> 5;

  for (int i=tid;i<32*64;i+=512) s.wp[i>>6][i&63] = WP2[i];
  for (int i=tid;i<64*32;i+=512) s.wq[i>>5][i&31] = WQ2[i];
  if (tid < 32) s.nw[tid] = w2[tid];
  __syncthreads();

  const unsigned aB = su32(&s.A[0][0]);
  const unsigned hB = su32(&s.H[0][0]);
  const unsigned pB = su32(&s.wp[0][0]);
  const unsigned qB = su32(&s.wq[0][0]);

  for (int tile = blockIdx.x; tile < NTILES; tile += gridDim.x){
    const int n0 = tile * ROWS;
    { // ---- load + RMS norm; scatter into (n*5+m, c) ----
      const int row = tid >> 3, sub = tid & 7;
      const float4* xr = reinterpret_cast<const float4*>(x + (size_t)(n0+row)*XDIM + 320 + sub*20);
      float4 w[5];
      #pragma unroll
      for (int j=0;j<5;j++) w[j] = xr[j];
      float vv[20] = {w[0].x,w[0].y,w[0].z,w[0].w, w[1].x,w[1].y,w[1].z,w[1].w,
                      w[2].x,w[2].y,w[2].z,w[2].w, w[3].x,w[3].y,w[3].z,w[3].w,
                      w[4].x,w[4].y,w[4].z,w[4].w};
      float sq = 0.f;
      #pragma unroll
      for (int j=0;j<20;j++) sq += vv[j]*vv[j];
      #pragma unroll
      for (int o=1;o<8;o<<=1) sq += __shfl_xor_sync(~0u, sq, o);
      float rinv = rsqrtf(sq*(1.f/32.f) + 1e-5f);
      float4* xd = reinterpret_cast<float4*>(&s.xs[row][sub*20]);
      #pragma unroll
      for (int j=0;j<5;j++) xd[j] = w[j];
      #pragma unroll
      for (int j=0;j<20;j++){
        int c = sub*4 + j/5, m = j - 5*(j/5);
        s.A[row*5 + m][c] = __float2half(vv[j]*rinv*s.nw[c]);
      }
    }
    __syncthreads();
    // ---- GEMM1: H(raw) = A[320x32] @ wp[32x64]; 80 tiles of 16x16 ----
    #pragma unroll
    for (int tt=0;tt<5;tt++){
      const int ti = warp + 16*tt;
      const int r0 = (ti>>2)<<4, c0 = (ti&3)<<4;
      float acc[2][4];
      #pragma unroll
      for (int j=0;j<2;j++){ acc[j][0]=acc[j][1]=acc[j][2]=acc[j][3]=0.f; }
      #pragma unroll
      for (int k=0;k<2;k++){
        unsigned a0,a1,a2,a3;
        ldmx4(a0,a1,a2,a3, aaddr(aB,40,r0,k*16,lane));
        unsigned b0,b1,b2,b3;
        ldmx4t(b0,b1,b2,b3, baddr(pB,72,k*16,c0,lane));
        mma16816(acc[0], a0,a1,a2,a3, b0,b1);
        mma16816(acc[1], a0,a1,a2,a3, b2,b3);
      }
      const int rr = r0 + (lane>>2), cc = c0 + ((lane&3)<<1);
      #pragma unroll
      for (int j=0;j<2;j++){
        *reinterpret_cast<__half2*>(&s.H[rr  ][cc+8*j]) = __floats2half2_rn(acc[j][0], acc[j][1]);
        *reinterpret_cast<__half2*>(&s.H[rr+8][cc+8*j]) = __floats2half2_rn(acc[j][2], acc[j][3]);
      }
    }
    __syncthreads();
    // ---- gate: per (n,o) across 5 m's ----
    #pragma unroll
    for (int it=0; it<8; it++){
      int i = tid + it*512;            // 64*64 elems
      int n = i >> 6, o = i & 63;
      float h[5];
      #pragma unroll
      for (int m=0;m<5;m++) h[m] = __half2float(s.H[5*n+m][o]);
      float g = sigm(sqrtf(h[0]*h[0]+h[1]*h[1]+h[2]*h[2]+h[3]*h[3]+h[4]*h[4] + 1e-12f));
      #pragma unroll
      for (int m=0;m<5;m++) s.H[5*n+m][o] = __float2half(h[m]*g);
    }
    __syncthreads();
    // ---- GEMM2: Y = H[320x64] @ wq[64x32]; 40 tiles of 16x16 ----
    float acc2[3][2][4];
    #pragma unroll
    for (int tt=0;tt<3;tt++)
      #pragma unroll
      for (int j=0;j<2;j++){ acc2[tt][j][0]=acc2[tt][j][1]=acc2[tt][j][2]=acc2[tt][j][3]=0.f; }
    #pragma unroll
    for (int tt=0;tt<3;tt++){
      const int ti = warp + 16*tt;
      if (ti < 40){
        const int r0 = (ti>>1)<<4, c0 = (ti&1)<<4;
        #pragma unroll
        for (int k=0;k<4;k++){
          unsigned a0,a1,a2,a3;
          ldmx4(a0,a1,a2,a3, aaddr(hB,72,r0,k*16,lane));
          unsigned b0,b1,b2,b3;
          ldmx4t(b0,b1,b2,b3, baddr(qB,40,k*16,c0,lane));
          mma16816(acc2[tt][0], a0,a1,a2,a3, b0,b1);
          mma16816(acc2[tt][1], a0,a1,a2,a3, b2,b3);
        }
      }
    }
    __syncthreads();   // H reads done
    { // ---- residual, re-layout (n*5+m, c) -> (n, c*5+m) ----
      float* ob = reinterpret_cast<float*>(&s.H[0][0]);
      #pragma unroll
      for (int tt=0;tt<3;tt++){
        const int ti = warp + 16*tt;
        if (ti < 40){
          const int r0 = (ti>>1)<<4, c0 = (ti&1)<<4;
          const int rr = r0 + (lane>>2), cc = c0 + ((lane&3)<<1);
          #pragma unroll
          for (int j=0;j<2;j++){
            int c = cc + 8*j;
            #pragma unroll
            for (int h=0;h<2;h++){
              int r = rr + 8*h;
              int n = r/5, m = r - 5*(r/5);
              ob[n*164 + c*5 + m]     = acc2[tt][j][2*h]   + s.xs[n][c*5 + m];
              ob[n*164 + (c+1)*5 + m] = acc2[tt][j][2*h+1] + s.xs[n][(c+1)*5 + m];
            }
          }
        }
      }
    }
    __syncthreads();
    { // ---- coalesced store ----
      const float* ob = reinterpret_cast<const float*>(&s.H[0][0]);
      #pragma unroll
      for (int i=0;i<5;i++){
        int idx = tid + i*512;          // 64 rows * 40 float4
        int row = idx/40, q = idx - 40*row;
        float4 v = *reinterpret_cast<const float4*>(&ob[row*164 + q*4]);
        *reinterpret_cast<float4*>(out + (size_t)(n0+row)*XDIM + 320 + q*4) = v;
      }
    }
    __syncthreads();
  }
}

extern "C" void kernel_launch(void* const* d_in, const int* in_sizes, int n_in,
                              void* d_out, int out_size){
  const float* x   = (const float*)d_in[0];
  const float* nw0 = (const float*)d_in[1];
  const float* nb0 = (const float*)d_in[2];
  const float* nw1 = (const float*)d_in[3];
  const float* nw2 = (const float*)d_in[4];
  const float* p0  = (const float*)d_in[5];
  const float* p1  = (const float*)d_in[6];
  const float* p2  = (const float*)d_in[7];
  const float* q0  = (const float*)d_in[8];
  const float* q1  = (const float*)d_in[9];
  const float* q2  = (const float*)d_in[10];
  float* out = (float*)d_out;

  cudaFuncSetAttribute(k_l0, cudaFuncAttributeMaxDynamicSharedMemorySize, (int)sizeof(SL0));
  cudaFuncSetAttribute(k_l1, cudaFuncAttributeMaxDynamicSharedMemorySize, (int)sizeof(SL1));
  cudaFuncSetAttribute(k_l2, cudaFuncAttributeMaxDynamicSharedMemorySize, (int)sizeof(SL2));

  k_prep<<<96, 256>>>(p0, p1, p2, q0, q1, q2);
  k_l0<<<GRID, 512, sizeof(SL0)>>>(x, out, nw0, nb0);
  k_l1<<<GRID, 512, sizeof(SL1)>>>(x, out, nw1);
  k_l2<<<GRID, 512, sizeof(SL2)>>>(x, out, nw2);
}

// round 3
// speedup vs baseline: 1.1041x; 1.1041x over previous
#include <cuda_runtime.h>
#include <cuda_fp16.h>
#include <cstdint>

#define NROW 200000
#define XDIM 480
#define ROWS 64
#define NTILES (NROW / ROWS)   // 3125 exactly
#define GRID 152
#define NTHR 1024

#define DINL __device__ __forceinline__

DINL unsigned su32(const void* p){ return (unsigned)__cvta_generic_to_shared(p); }

DINL void ldmx4(unsigned &r0,unsigned &r1,unsigned &r2,unsigned &r3, unsigned a){
  asm volatile("ldmatrix.sync.aligned.m8n8.x4.shared.b16 {%0,%1,%2,%3}, [%4];"
    : "=r"(r0),"=r"(r1),"=r"(r2),"=r"(r3) : "r"(a));
}
DINL void ldmx4t(unsigned &r0,unsigned &r1,unsigned &r2,unsigned &r3, unsigned a){
  asm volatile("ldmatrix.sync.aligned.m8n8.x4.trans.shared.b16 {%0,%1,%2,%3}, [%4];"
    : "=r"(r0),"=r"(r1),"=r"(r2),"=r"(r3) : "r"(a));
}
DINL void mma16816(float* c, unsigned a0,unsigned a1,unsigned a2,unsigned a3,
                   unsigned b0,unsigned b1){
  asm volatile("mma.sync.aligned.m16n8k16.row.col.f32.f16.f16.f32 "
    "{%0,%1,%2,%3}, {%4,%5,%6,%7}, {%8,%9}, {%0,%1,%2,%3};"
    : "+f"(c[0]),"+f"(c[1]),"+f"(c[2]),"+f"(c[3])
    : "r"(a0),"r"(a1),"r"(a2),"r"(a3),"r"(b0),"r"(b1));
}
DINL float sigm(float v){ return 1.f/(1.f+__expf(-v)); }

DINL unsigned aaddr(unsigned base, int stride, int r0, int k0, int lane){
  int r = r0 + (lane & 15);
  int c = k0 + ((lane >> 4) << 3);
  return base + (unsigned)((r * stride + c) << 1);
}
DINL unsigned baddr(unsigned base, int stride, int k0, int c0, int lane){
  int r = k0 + (lane & 7) + (((lane >> 3) & 1) << 3);
  int c = c0 + ((lane >> 4) << 3);
  return base + (unsigned)((r * stride + c) << 1);
}

// fp16 weights with 1/sqrt(fan_in) folded
__device__ __half WP0[128*256];
__device__ __half WQ0[256*128];
__device__ __half WP1[64*128];
__device__ __half WQ1[128*64];
__device__ __half WP2[32*64];
__device__ __half WQ2[64*32];

__global__ void k_prep(const float* __restrict__ p0, const float* __restrict__ p1,
                       const float* __restrict__ p2, const float* __restrict__ q0,
                       const float* __restrict__ q1, const float* __restrict__ q2){
  int t = blockIdx.x*blockDim.x + threadIdx.x, st = gridDim.x*blockDim.x;
  for (int i=t;i<128*256;i+=st) WP0[i] = __float2half(p0[i]*0.08838834764831845f);
  for (int i=t;i<64*128;i+=st)  WP1[i] = __float2half(p1[i]*0.125f);
  for (int i=t;i<32*64;i+=st)   WP2[i] = __float2half(p2[i]*0.17677669529663687f);
  for (int i=t;i<256*128;i+=st) WQ0[i] = __float2half(q0[i]*0.0625f);
  for (int i=t;i<128*64;i+=st)  WQ1[i] = __float2half(q1[i]*0.08838834764831845f);
  for (int i=t;i<64*32;i+=st)   WQ2[i] = __float2half(q2[i]*0.125f);
}

// ============================ l = 0 ============================
struct SL0 {
  float  nw[128], nb[128];
  __half wp[128][264];
  __half wq[256][136];
  __half A[64][136];
  __half H[64][264];
};

__global__ __launch_bounds__(NTHR,1) void k_l0(const float* __restrict__ x,
                                               float* __restrict__ out,
                                               const float* __restrict__ w0,
                                               const float* __restrict__ b0){
  extern __shared__ __align__(16) char smem[];
  SL0& s = *reinterpret_cast<SL0*>(smem);
  const int tid = threadIdx.x, lane = tid & 31, warp = tid >> 5;

  for (int i=tid;i<128*256;i+=NTHR) s.wp[i>>8][i&255] = WP0[i];
  for (int i=tid;i<256*128;i+=NTHR) s.wq[i>>7][i&127] = WQ0[i];
  if (tid < 128){ s.nw[tid] = w0[tid]; s.nb[tid] = b0[tid]; }
  __syncthreads();

  const unsigned aB = su32(&s.A[0][0]);
  const unsigned hB = su32(&s.H[0][0]);
  const unsigned pB = su32(&s.wp[0][0]);
  const unsigned qB = su32(&s.wq[0][0]);

  const int r0  = (warp >> 3) << 4;  // 0..48
  const int c0  = (warp & 7) << 5;   // GEMM1 cols (32 wide)
  const int c0b = (warp & 7) << 4;   // GEMM2 cols (16 wide)

  for (int tile = blockIdx.x; tile < NTILES; tile += gridDim.x){
    const int n0 = tile * ROWS;
    { // ---- load + layernorm (16 threads per row, 8 floats each) ----
      const int row = tid >> 4, sub = tid & 15;
      const float4* xr = reinterpret_cast<const float4*>(x + (size_t)(n0+row)*XDIM + sub*8);
      float4 v0 = xr[0], v1 = xr[1];
      float vv[8] = {v0.x,v0.y,v0.z,v0.w, v1.x,v1.y,v1.z,v1.w};
      float sm = 0.f, sq = 0.f;
      #pragma unroll
      for (int j=0;j<8;j++){ sm += vv[j]; sq += vv[j]*vv[j]; }
      #pragma unroll
      for (int o=1;o<16;o<<=1){ sm += __shfl_xor_sync(~0u, sm, o); sq += __shfl_xor_sync(~0u, sq, o); }
      float mu = sm * (1.f/128.f);
      float rinv = rsqrtf(sq*(1.f/128.f) - mu*mu + 1e-5f);
      const int cb = sub*8;
      __half2 h[4];
      #pragma unroll
      for (int j=0;j<4;j++){
        float a0f = (vv[2*j]   - mu)*rinv*s.nw[cb+2*j]   + s.nb[cb+2*j];
        float a1f = (vv[2*j+1] - mu)*rinv*s.nw[cb+2*j+1] + s.nb[cb+2*j+1];
        h[j] = __floats2half2_rn(a0f, a1f);
      }
      *reinterpret_cast<uint4*>(&s.A[row][cb]) = *reinterpret_cast<uint4*>(h);
    }
    __syncthreads();
    { // ---- GEMM1 + sigmoid -> H (tiles 16x32) ----
      float acc[4][4];
      #pragma unroll
      for (int j=0;j<4;j++){ acc[j][0]=acc[j][1]=acc[j][2]=acc[j][3]=0.f; }
      #pragma unroll
      for (int k=0;k<8;k++){
        unsigned a0,a1,a2,a3;
        ldmx4(a0,a1,a2,a3, aaddr(aB,136,r0,k*16,lane));
        #pragma unroll
        for (int j=0;j<2;j++){
          unsigned b0,b1,b2,b3;
          ldmx4t(b0,b1,b2,b3, baddr(pB,264,k*16,c0+j*16,lane));
          mma16816(acc[2*j],   a0,a1,a2,a3, b0,b1);
          mma16816(acc[2*j+1], a0,a1,a2,a3, b2,b3);
        }
      }
      const int rr = r0 + (lane>>2), cc = c0 + ((lane&3)<<1);
      #pragma unroll
      for (int j=0;j<4;j++){
        *reinterpret_cast<__half2*>(&s.H[rr  ][cc+8*j]) = __floats2half2_rn(sigm(acc[j][0]), sigm(acc[j][1]));
        *reinterpret_cast<__half2*>(&s.H[rr+8][cc+8*j]) = __floats2half2_rn(sigm(acc[j][2]), sigm(acc[j][3]));
      }
    }
    __syncthreads();
    { // ---- GEMM2 (tiles 16x16) + direct residual epilogue ----
      float acc2[2][4];
      #pragma unroll
      for (int j=0;j<2;j++){ acc2[j][0]=acc2[j][1]=acc2[j][2]=acc2[j][3]=0.f; }
      #pragma unroll
      for (int k=0;k<16;k++){
        unsigned a0,a1,a2,a3;
        ldmx4(a0,a1,a2,a3, aaddr(hB,264,r0,k*16,lane));
        unsigned b0,b1,b2,b3;
        ldmx4t(b0,b1,b2,b3, baddr(qB,136,k*16,c0b,lane));
        mma16816(acc2[0], a0,a1,a2,a3, b0,b1);
        mma16816(acc2[1], a0,a1,a2,a3, b2,b3);
      }
      const int rr = r0 + (lane>>2), cc = c0b + ((lane&3)<<1);
      #pragma unroll
      for (int j=0;j<2;j++){
        int c = cc + 8*j;
        size_t i0 = (size_t)(n0+rr)*XDIM + c;
        size_t i1 = (size_t)(n0+rr+8)*XDIM + c;
        float2 xv0 = *reinterpret_cast<const float2*>(x + i0);
        float2 xv1 = *reinterpret_cast<const float2*>(x + i1);
        float2 o0 = make_float2(acc2[j][0]+xv0.x, acc2[j][1]+xv0.y);
        float2 o1 = make_float2(acc2[j][2]+xv1.x, acc2[j][3]+xv1.y);
        *reinterpret_cast<float2*>(out + i0) = o0;
        *reinterpret_cast<float2*>(out + i1) = o1;
      }
    }
    __syncthreads();   // protect A and H for next tile
  }
}

// ============================ l = 1 ============================
struct SL1 {
  float  xs[64][196];
  float  nw[64];
  __half wp[64][136];
  __half wq[128][72];
  __half A[192][72];
  __half H[192][136];   // reused as float[64][196] out buffer
};

__global__ __launch_bounds__(NTHR,1) void k_l1(const float* __restrict__ x,
                                               float* __restrict__ out,
                                               const float* __restrict__ w1){
  extern __shared__ __align__(16) char smem[];
  SL1& s = *reinterpret_cast<SL1*>(smem);
  const int tid = threadIdx.x, lane = tid & 31, warp = tid >> 5;

  for (int i=tid;i<64*128;i+=NTHR) s.wp[i>>7][i&127] = WP1[i];
  for (int i=tid;i<128*64;i+=NTHR) s.wq[i>>6][i&63]  = WQ1[i];
  if (tid < 64) s.nw[tid] = w1[tid];
  __syncthreads();

  const unsigned aB = su32(&s.A[0][0]);
  const unsigned hB = su32(&s.H[0][0]);
  const unsigned pB = su32(&s.wp[0][0]);
  const unsigned qB = su32(&s.wq[0][0]);

  for (int tile = blockIdx.x; tile < NTILES; tile += gridDim.x){
    const int n0 = tile * ROWS;
    { // ---- load + RMS norm (16 thr/row, 12 floats each) ----
      const int row = tid >> 4, sub = tid & 15;
      const float4* xr = reinterpret_cast<const float4*>(x + (size_t)(n0+row)*XDIM + 128 + sub*12);
      float4 w[3];
      #pragma unroll
      for (int j=0;j<3;j++) w[j] = xr[j];
      float vv[12] = {w[0].x,w[0].y,w[0].z,w[0].w, w[1].x,w[1].y,w[1].z,w[1].w,
                      w[2].x,w[2].y,w[2].z,w[2].w};
      float sq = 0.f;
      #pragma unroll
      for (int j=0;j<12;j++) sq += vv[j]*vv[j];
      #pragma unroll
      for (int o=1;o<16;o<<=1) sq += __shfl_xor_sync(~0u, sq, o);
      float rinv = rsqrtf(sq*(1.f/64.f) + 1e-5f);
      float4* xd = reinterpret_cast<float4*>(&s.xs[row][sub*12]);
      #pragma unroll
      for (int j=0;j<3;j++) xd[j] = w[j];
      #pragma unroll
      for (int j=0;j<12;j++){
        int c = sub*4 + j/3, m = j - 3*(j/3);
        s.A[row*3 + m][c] = __float2half(vv[j]*rinv*s.nw[c]);
      }
    }
    __syncthreads();
    // ---- GEMM1: H = A[192x64] @ wp[64x128]; 96 tiles 16x16 ----
    #pragma unroll
    for (int tt=0;tt<3;tt++){
      const int ti = warp + 32*tt;
      const int r0 = (ti>>3)<<4, c0 = (ti&7)<<4;
      float acc[2][4];
      #pragma unroll
      for (int j=0;j<2;j++){ acc[j][0]=acc[j][1]=acc[j][2]=acc[j][3]=0.f; }
      #pragma unroll
      for (int k=0;k<4;k++){
        unsigned a0,a1,a2,a3;
        ldmx4(a0,a1,a2,a3, aaddr(aB,72,r0,k*16,lane));
        unsigned b0,b1,b2,b3;
        ldmx4t(b0,b1,b2,b3, baddr(pB,136,k*16,c0,lane));
        mma16816(acc[0], a0,a1,a2,a3, b0,b1);
        mma16816(acc[1], a0,a1,a2,a3, b2,b3);
      }
      const int rr = r0 + (lane>>2), cc = c0 + ((lane&3)<<1);
      #pragma unroll
      for (int j=0;j<2;j++){
        *reinterpret_cast<__half2*>(&s.H[rr  ][cc+8*j]) = __floats2half2_rn(acc[j][0], acc[j][1]);
        *reinterpret_cast<__half2*>(&s.H[rr+8][cc+8*j]) = __floats2half2_rn(acc[j][2], acc[j][3]);
      }
    }
    __syncthreads();
    // ---- gate ----
    #pragma unroll
    for (int it=0; it<8; it++){
      int i = tid + it*NTHR;           // 64*128 elems
      int n = i >> 7, o = i & 127;
      float h0 = __half2float(s.H[3*n  ][o]);
      float h1 = __half2float(s.H[3*n+1][o]);
      float h2 = __half2float(s.H[3*n+2][o]);
      float g = sigm(sqrtf(h0*h0 + h1*h1 + h2*h2 + 1e-12f));
      s.H[3*n  ][o] = __float2half(h0*g);
      s.H[3*n+1][o] = __float2half(h1*g);
      s.H[3*n+2][o] = __float2half(h2*g);
    }
    __syncthreads();
    // ---- GEMM2: Y = H[192x128] @ wq[128x64]; 48 tiles 16x16 ----
    float acc2[2][2][4];
    #pragma unroll
    for (int tt=0;tt<2;tt++)
      #pragma unroll
      for (int j=0;j<2;j++){ acc2[tt][j][0]=acc2[tt][j][1]=acc2[tt][j][2]=acc2[tt][j][3]=0.f; }
    #pragma unroll
    for (int tt=0;tt<2;tt++){
      const int ti = warp + 32*tt;
      if (ti < 48){
        const int r0 = (ti>>2)<<4, c0 = (ti&3)<<4;
        #pragma unroll
        for (int k=0;k<8;k++){
          unsigned a0,a1,a2,a3;
          ldmx4(a0,a1,a2,a3, aaddr(hB,136,r0,k*16,lane));
          unsigned b0,b1,b2,b3;
          ldmx4t(b0,b1,b2,b3, baddr(qB,72,k*16,c0,lane));
          mma16816(acc2[tt][0], a0,a1,a2,a3, b0,b1);
          mma16816(acc2[tt][1], a0,a1,a2,a3, b2,b3);
        }
      }
    }
    __syncthreads();   // H reads done
    { // ---- residual + re-layout into ob (reuse H) ----
      float* ob = reinterpret_cast<float*>(&s.H[0][0]);
      #pragma unroll
      for (int tt=0;tt<2;tt++){
        const int ti = warp + 32*tt;
        if (ti < 48){
          const int r0 = (ti>>2)<<4, c0 = (ti&3)<<4;
          const int rr = r0 + (lane>>2), cc = c0 + ((lane&3)<<1);
          #pragma unroll
          for (int j=0;j<2;j++){
            int c = cc + 8*j;
            #pragma unroll
            for (int h=0;h<2;h++){
              int r = rr + 8*h;
              int n = r/3, m = r - 3*(r/3);
              ob[n*196 + c*3 + m]     = acc2[tt][j][2*h]   + s.xs[n][c*3 + m];
              ob[n*196 + (c+1)*3 + m] = acc2[tt][j][2*h+1] + s.xs[n][(c+1)*3 + m];
            }
          }
        }
      }
    }
    __syncthreads();
    { // ---- coalesced store ----
      const float* ob = reinterpret_cast<const float*>(&s.H[0][0]);
      #pragma unroll
      for (int i=0;i<3;i++){
        int idx = tid + i*NTHR;          // 64 rows * 48 float4
        int row = idx/48, q = idx - 48*row;
        float4 v = *reinterpret_cast<const float4*>(&ob[row*196 + q*4]);
        *reinterpret_cast<float4*>(out + (size_t)(n0+row)*XDIM + 128 + q*4) = v;
      }
    }
    __syncthreads();
  }
}

// ============================ l = 2 ============================
struct SL2 {
  float  xs[64][164];
  float  nw[32];
  __half wp[32][72];
  __half wq[64][40];
  __half A[320][40];
  __half H[320][72];    // reused as float[64][164] out buffer
};

__global__ __launch_bounds__(NTHR,1) void k_l2(const float* __restrict__ x,
                                               float* __restrict__ out,
                                               const float* __restrict__ w2){
  extern __shared__ __align__(16) char smem[];
  SL2& s = *reinterpret_cast<SL2*>(smem);
  const int tid = threadIdx.x, lane = tid & 31, warp = tid >> 5;

  for (int i=tid;i<32*64;i+=NTHR) s.wp[i>>6][i&63] = WP2[i];
  for (int i=tid;i<64*32;i+=NTHR) s.wq[i>>5][i&31] = WQ2[i];
  if (tid < 32) s.nw[tid] = w2[tid];
  __syncthreads();

  const unsigned aB = su32(&s.A[0][0]);
  const unsigned hB = su32(&s.H[0][0]);
  const unsigned pB = su32(&s.wp[0][0]);
  const unsigned qB = su32(&s.wq[0][0]);

  for (int tile = blockIdx.x; tile < NTILES; tile += gridDim.x){
    const int n0 = tile * ROWS;
    { // ---- load + RMS norm (16 thr/row, 10 floats each via float2) ----
      const int row = tid >> 4, sub = tid & 15;
      const float2* xr = reinterpret_cast<const float2*>(x + (size_t)(n0+row)*XDIM + 320 + sub*10);
      float2 w[5];
      #pragma unroll
      for (int j=0;j<5;j++) w[j] = xr[j];
      float vv[10] = {w[0].x,w[0].y, w[1].x,w[1].y, w[2].x,w[2].y,
                      w[3].x,w[3].y, w[4].x,w[4].y};
      float sq = 0.f;
      #pragma unroll
      for (int j=0;j<10;j++) sq += vv[j]*vv[j];
      #pragma unroll
      for (int o=1;o<16;o<<=1) sq += __shfl_xor_sync(~0u, sq, o);
      float rinv = rsqrtf(sq*(1.f/32.f) + 1e-5f);
      float2* xd = reinterpret_cast<float2*>(&s.xs[row][sub*10]);
      #pragma unroll
      for (int j=0;j<5;j++) xd[j] = w[j];
      #pragma unroll
      for (int j=0;j<10;j++){
        int c = sub*2 + j/5, m = j - 5*(j/5);
        s.A[row*5 + m][c] = __float2half(vv[j]*rinv*s.nw[c]);
      }
    }
    __syncthreads();
    // ---- GEMM1: H = A[320x32] @ wp[32x64]; 80 tiles 16x16 ----
    #pragma unroll
    for (int tt=0;tt<3;tt++){
      const int ti = warp + 32*tt;
      if (ti < 80){
        const int r0 = (ti>>2)<<4, c0 = (ti&3)<<4;
        float acc[2][4];
        #pragma unroll
        for (int j=0;j<2;j++){ acc[j][0]=acc[j][1]=acc[j][2]=acc[j][3]=0.f; }
        #pragma unroll
        for (int k=0;k<2;k++){
          unsigned a0,a1,a2,a3;
          ldmx4(a0,a1,a2,a3, aaddr(aB,40,r0,k*16,lane));
          unsigned b0,b1,b2,b3;
          ldmx4t(b0,b1,b2,b3, baddr(pB,72,k*16,c0,lane));
          mma16816(acc[0], a0,a1,a2,a3, b0,b1);
          mma16816(acc[1], a0,a1,a2,a3, b2,b3);
        }
        const int rr = r0 + (lane>>2), cc = c0 + ((lane&3)<<1);
        #pragma unroll
        for (int j=0;j<2;j++){
          *reinterpret_cast<__half2*>(&s.H[rr  ][cc+8*j]) = __floats2half2_rn(acc[j][0], acc[j][1]);
          *reinterpret_cast<__half2*>(&s.H[rr+8][cc+8*j]) = __floats2half2_rn(acc[j][2], acc[j][3]);
        }
      }
    }
    __syncthreads();
    // ---- gate ----
    #pragma unroll
    for (int it=0; it<4; it++){
      int i = tid + it*NTHR;           // 64*64 elems
      int n = i >> 6, o = i & 63;
      float h[5];
      #pragma unroll
      for (int m=0;m<5;m++) h[m] = __half2float(s.H[5*n+m][o]);
      float g = sigm(sqrtf(h[0]*h[0]+h[1]*h[1]+h[2]*h[2]+h[3]*h[3]+h[4]*h[4] + 1e-12f));
      #pragma unroll
      for (int m=0;m<5;m++) s.H[5*n+m][o] = __float2half(h[m]*g);
    }
    __syncthreads();
    // ---- GEMM2: Y = H[320x64] @ wq[64x32]; 40 tiles 16x16 ----
    float acc2[2][2][4];
    #pragma unroll
    for (int tt=0;tt<2;tt++)
      #pragma unroll
      for (int j=0;j<2;j++){ acc2[tt][j][0]=acc2[tt][j][1]=acc2[tt][j][2]=acc2[tt][j][3]=0.f; }
    #pragma unroll
    for (int tt=0;tt<2;tt++){
      const int ti = warp + 32*tt;
      if (ti < 40){
        const int r0 = (ti>>1)<<4, c0 = (ti&1)<<4;
        #pragma unroll
        for (int k=0;k<4;k++){
          unsigned a0,a1,a2,a3;
          ldmx4(a0,a1,a2,a3, aaddr(hB,72,r0,k*16,lane));
          unsigned b0,b1,b2,b3;
          ldmx4t(b0,b1,b2,b3, baddr(qB,40,k*16,c0,lane));
          mma16816(acc2[tt][0], a0,a1,a2,a3, b0,b1);
          mma16816(acc2[tt][1], a0,a1,a2,a3, b2,b3);
        }
      }
    }
    __syncthreads();   // H reads done
    { // ---- residual + re-layout into ob ----
      float* ob = reinterpret_cast<float*>(&s.H[0][0]);
      #pragma unroll
      for (int tt=0;tt<2;tt++){
        const int ti = warp + 32*tt;
        if (ti < 40){
          const int r0 = (ti>>1)<<4, c0 = (ti&1)<<4;
          const int rr = r0 + (lane>>2), cc = c0 + ((lane&3)<<1);
          #pragma unroll
          for (int j=0;j<2;j++){
            int c = cc + 8*j;
            #pragma unroll
            for (int h=0;h<2;h++){
              int r = rr + 8*h;
              int n = r/5, m = r - 5*(r/5);
              ob[n*164 + c*5 + m]     = acc2[tt][j][2*h]   + s.xs[n][c*5 + m];
              ob[n*164 + (c+1)*5 + m] = acc2[tt][j][2*h+1] + s.xs[n][(c+1)*5 + m];
            }
          }
        }
      }
    }
    __syncthreads();
    { // ---- coalesced store ----
      const float* ob = reinterpret_cast<const float*>(&s.H[0][0]);
      #pragma unroll
      for (int i=0;i<3;i++){
        int idx = tid + i*NTHR;          // 64 rows * 40 float4 = 2560
        if (idx < 2560){
          int row = idx/40, q = idx - 40*row;
          float4 v = *reinterpret_cast<const float4*>(&ob[row*164 + q*4]);
          *reinterpret_cast<float4*>(out + (size_t)(n0+row)*XDIM + 320 + q*4) = v;
        }
      }
    }
    __syncthreads();
  }
}

extern "C" void kernel_launch(void* const* d_in, const int* in_sizes, int n_in,
                              void* d_out, int out_size){
  const float* x   = (const float*)d_in[0];
  const float* nw0 = (const float*)d_in[1];
  const float* nb0 = (const float*)d_in[2];
  const float* nw1 = (const float*)d_in[3];
  const float* nw2 = (const float*)d_in[4];
  const float* p0  = (const float*)d_in[5];
  const float* p1  = (const float*)d_in[6];
  const float* p2  = (const float*)d_in[7];
  const float* q0  = (const float*)d_in[8];
  const float* q1  = (const float*)d_in[9];
  const float* q2  = (const float*)d_in[10];
  float* out = (float*)d_out;

  cudaFuncSetAttribute(k_l0, cudaFuncAttributeMaxDynamicSharedMemorySize, (int)sizeof(SL0));
  cudaFuncSetAttribute(k_l1, cudaFuncAttributeMaxDynamicSharedMemorySize, (int)sizeof(SL1));
  cudaFuncSetAttribute(k_l2, cudaFuncAttributeMaxDynamicSharedMemorySize, (int)sizeof(SL2));

  k_prep<<<96, 256>>>(p0, p1, p2, q0, q1, q2);
  k_l0<<<GRID, NTHR, sizeof(SL0)>>>(x, out, nw0, nb0);
  k_l1<<<GRID, NTHR, sizeof(SL1)>>>(x, out, nw1);
  k_l2<<<GRID, NTHR, sizeof(SL2)>>>(x, out, nw2);
}

// round 4
// speedup vs baseline: 1.1417x; 1.0340x over previous
#include <cuda_runtime.h>
#include <cuda_fp16.h>
#include <cstdint>

#define NROW 200000
#define XDIM 480
#define ROWS 64
#define NTILES (NROW / ROWS)   // 3125 exactly
#define GRID 152
#define NTHR 1024

#define DINL __device__ __forceinline__

DINL unsigned su32(const void* p){ return (unsigned)__cvta_generic_to_shared(p); }

DINL void cpasync16(unsigned dst, const void* src){
  asm volatile("cp.async.ca.shared.global [%0], [%1], 16;" :: "r"(dst), "l"(src));
}
DINL void cpcommit(){ asm volatile("cp.async.commit_group;" ::: "memory"); }
DINL void cpwait0(){ asm volatile("cp.async.wait_group 0;" ::: "memory"); }
DINL void cpwait1(){ asm volatile("cp.async.wait_group 1;" ::: "memory"); }

DINL void ldmx4(unsigned &r0,unsigned &r1,unsigned &r2,unsigned &r3, unsigned a){
  asm volatile("ldmatrix.sync.aligned.m8n8.x4.shared.b16 {%0,%1,%2,%3}, [%4];"
    : "=r"(r0),"=r"(r1),"=r"(r2),"=r"(r3) : "r"(a));
}
DINL void ldmx4t(unsigned &r0,unsigned &r1,unsigned &r2,unsigned &r3, unsigned a){
  asm volatile("ldmatrix.sync.aligned.m8n8.x4.trans.shared.b16 {%0,%1,%2,%3}, [%4];"
    : "=r"(r0),"=r"(r1),"=r"(r2),"=r"(r3) : "r"(a));
}
DINL void mma16816(float* c, unsigned a0,unsigned a1,unsigned a2,unsigned a3,
                   unsigned b0,unsigned b1){
  asm volatile("mma.sync.aligned.m16n8k16.row.col.f32.f16.f16.f32 "
    "{%0,%1,%2,%3}, {%4,%5,%6,%7}, {%8,%9}, {%0,%1,%2,%3};"
    : "+f"(c[0]),"+f"(c[1]),"+f"(c[2]),"+f"(c[3])
    : "r"(a0),"r"(a1),"r"(a2),"r"(a3),"r"(b0),"r"(b1));
}
DINL float sigm(float v){ return 1.f/(1.f+__expf(-v)); }

DINL unsigned aaddr(unsigned base, int stride, int r0, int k0, int lane){
  int r = r0 + (lane & 15);
  int c = k0 + ((lane >> 4) << 3);
  return base + (unsigned)((r * stride + c) << 1);
}
DINL unsigned baddr(unsigned base, int stride, int k0, int c0, int lane){
  int r = k0 + (lane & 7) + (((lane >> 3) & 1) << 3);
  int c = c0 + ((lane >> 4) << 3);
  return base + (unsigned)((r * stride + c) << 1);
}

// fp16 weights with 1/sqrt(fan_in) folded
__device__ __half WP0[128*256];
__device__ __half WQ0[256*128];
__device__ __half WP1[64*128];
__device__ __half WQ1[128*64];
__device__ __half WP2[32*64];
__device__ __half WQ2[64*32];

__global__ void k_prep(const float* __restrict__ p0, const float* __restrict__ p1,
                       const float* __restrict__ p2, const float* __restrict__ q0,
                       const float* __restrict__ q1, const float* __restrict__ q2){
  int t = blockIdx.x*blockDim.x + threadIdx.x, st = gridDim.x*blockDim.x;
  for (int i=t;i<128*256;i+=st) WP0[i] = __float2half(p0[i]*0.08838834764831845f);
  for (int i=t;i<64*128;i+=st)  WP1[i] = __float2half(p1[i]*0.125f);
  for (int i=t;i<32*64;i+=st)   WP2[i] = __float2half(p2[i]*0.17677669529663687f);
  for (int i=t;i<256*128;i+=st) WQ0[i] = __float2half(q0[i]*0.0625f);
  for (int i=t;i<128*64;i+=st)  WQ1[i] = __float2half(q1[i]*0.08838834764831845f);
  for (int i=t;i<64*32;i+=st)   WQ2[i] = __float2half(q2[i]*0.125f);
}

// ============================ l = 0 ============================
struct SL0 {
  float  nw[128], nb[128];
  __half wp[128][264];
  __half wq[256][136];
  __half A[64][136];
  __half H[64][264];
  float  xb[64][132];        // cp.async staging (single buffer)
};

DINL void l0_prefetch(SL0& s, const float* x, int n0, int tid){
  #pragma unroll
  for (int i = tid; i < 2048; i += NTHR){      // 64 rows * 32 float4
    int row = i >> 5, q = i & 31;
    cpasync16(su32(&s.xb[row][q*4]), x + (size_t)(n0+row)*XDIM + q*4);
  }
}

__global__ __launch_bounds__(NTHR,1) void k_l0(const float* __restrict__ x,
                                               float* __restrict__ out,
                                               const float* __restrict__ w0,
                                               const float* __restrict__ b0){
  extern __shared__ __align__(16) char smem[];
  SL0& s = *reinterpret_cast<SL0*>(smem);
  const int tid = threadIdx.x, lane = tid & 31, warp = tid >> 5;

  for (int i=tid;i<128*256;i+=NTHR) s.wp[i>>8][i&255] = WP0[i];
  for (int i=tid;i<256*128;i+=NTHR) s.wq[i>>7][i&127] = WQ0[i];
  if (tid < 128){ s.nw[tid] = w0[tid]; s.nb[tid] = b0[tid]; }

  l0_prefetch(s, x, blockIdx.x * ROWS, tid);
  cpcommit();

  const unsigned aB = su32(&s.A[0][0]);
  const unsigned hB = su32(&s.H[0][0]);
  const unsigned pB = su32(&s.wp[0][0]);
  const unsigned qB = su32(&s.wq[0][0]);

  const int r0  = (warp >> 3) << 4;
  const int c0  = (warp & 7) << 5;
  const int c0b = (warp & 7) << 4;

  for (int tile = blockIdx.x; tile < NTILES; tile += gridDim.x){
    const int n0 = tile * ROWS;
    cpwait0();
    __syncthreads();           // xb ready (also: prev tile's A/H reads done)
    { // ---- norm from xb ----
      const int row = tid >> 4, sub = tid & 15;
      float4 v0 = *reinterpret_cast<const float4*>(&s.xb[row][sub*8]);
      float4 v1 = *reinterpret_cast<const float4*>(&s.xb[row][sub*8+4]);
      float vv[8] = {v0.x,v0.y,v0.z,v0.w, v1.x,v1.y,v1.z,v1.w};
      float sm = 0.f, sq = 0.f;
      #pragma unroll
      for (int j=0;j<8;j++){ sm += vv[j]; sq += vv[j]*vv[j]; }
      #pragma unroll
      for (int o=1;o<16;o<<=1){ sm += __shfl_xor_sync(~0u, sm, o); sq += __shfl_xor_sync(~0u, sq, o); }
      float mu = sm * (1.f/128.f);
      float rinv = rsqrtf(sq*(1.f/128.f) - mu*mu + 1e-5f);
      const int cb = sub*8;
      __half2 h[4];
      #pragma unroll
      for (int j=0;j<4;j++){
        float a0f = (vv[2*j]   - mu)*rinv*s.nw[cb+2*j]   + s.nb[cb+2*j];
        float a1f = (vv[2*j+1] - mu)*rinv*s.nw[cb+2*j+1] + s.nb[cb+2*j+1];
        h[j] = __floats2half2_rn(a0f, a1f);
      }
      *reinterpret_cast<uint4*>(&s.A[row][cb]) = *reinterpret_cast<uint4*>(h);
    }
    __syncthreads();           // A ready; xb reads done
    { // prefetch next tile while GEMMs run
      int nt = tile + gridDim.x;
      if (nt < NTILES) l0_prefetch(s, x, nt * ROWS, tid);
      cpcommit();
    }
    { // ---- GEMM1 + sigmoid -> H ----
      float acc[4][4];
      #pragma unroll
      for (int j=0;j<4;j++){ acc[j][0]=acc[j][1]=acc[j][2]=acc[j][3]=0.f; }
      #pragma unroll
      for (int k=0;k<8;k++){
        unsigned a0,a1,a2,a3;
        ldmx4(a0,a1,a2,a3, aaddr(aB,136,r0,k*16,lane));
        #pragma unroll
        for (int j=0;j<2;j++){
          unsigned b0,b1,b2,b3;
          ldmx4t(b0,b1,b2,b3, baddr(pB,264,k*16,c0+j*16,lane));
          mma16816(acc[2*j],   a0,a1,a2,a3, b0,b1);
          mma16816(acc[2*j+1], a0,a1,a2,a3, b2,b3);
        }
      }
      const int rr = r0 + (lane>>2), cc = c0 + ((lane&3)<<1);
      #pragma unroll
      for (int j=0;j<4;j++){
        *reinterpret_cast<__half2*>(&s.H[rr  ][cc+8*j]) = __floats2half2_rn(sigm(acc[j][0]), sigm(acc[j][1]));
        *reinterpret_cast<__half2*>(&s.H[rr+8][cc+8*j]) = __floats2half2_rn(sigm(acc[j][2]), sigm(acc[j][3]));
      }
    }
    __syncthreads();           // H ready
    { // ---- GEMM2 + direct residual epilogue ----
      float acc2[2][4];
      #pragma unroll
      for (int j=0;j<2;j++){ acc2[j][0]=acc2[j][1]=acc2[j][2]=acc2[j][3]=0.f; }
      #pragma unroll
      for (int k=0;k<16;k++){
        unsigned a0,a1,a2,a3;
        ldmx4(a0,a1,a2,a3, aaddr(hB,264,r0,k*16,lane));
        unsigned b0,b1,b2,b3;
        ldmx4t(b0,b1,b2,b3, baddr(qB,136,k*16,c0b,lane));
        mma16816(acc2[0], a0,a1,a2,a3, b0,b1);
        mma16816(acc2[1], a0,a1,a2,a3, b2,b3);
      }
      const int rr = r0 + (lane>>2), cc = c0b + ((lane&3)<<1);
      #pragma unroll
      for (int j=0;j<2;j++){
        int c = cc + 8*j;
        size_t i0 = (size_t)(n0+rr)*XDIM + c;
        size_t i1 = (size_t)(n0+rr+8)*XDIM + c;
        float2 xv0 = *reinterpret_cast<const float2*>(x + i0);
        float2 xv1 = *reinterpret_cast<const float2*>(x + i1);
        *reinterpret_cast<float2*>(out + i0) = make_float2(acc2[j][0]+xv0.x, acc2[j][1]+xv0.y);
        *reinterpret_cast<float2*>(out + i1) = make_float2(acc2[j][2]+xv1.x, acc2[j][3]+xv1.y);
      }
    }
    // loop-top barrier protects A/H for next tile
  }
}

// ============================ l = 1 ============================
struct SL1 {
  float  xb[2][64][196];     // ping-pong raw x staging (also residual source)
  float  nw[64];
  __half wp[64][136];
  __half wq[128][72];
  __half A[192][72];
  __half H[192][136];        // reused as float[64][196] out buffer
};

DINL void l1_prefetch(SL1& s, int b, const float* x, int n0, int tid){
  #pragma unroll
  for (int i = tid; i < 3072; i += NTHR){    // 64 rows * 48 float4
    int row = i/48, q = i - 48*row;
    cpasync16(su32(&s.xb[b][row][q*4]), x + (size_t)(n0+row)*XDIM + 128 + q*4);
  }
}

__global__ __launch_bounds__(NTHR,1) void k_l1(const float* __restrict__ x,
                                               float* __restrict__ out,
                                               const float* __restrict__ w1){
  extern __shared__ __align__(16) char smem[];
  SL1& s = *reinterpret_cast<SL1*>(smem);
  const int tid = threadIdx.x, lane = tid & 31, warp = tid >> 5;

  for (int i=tid;i<64*128;i+=NTHR) s.wp[i>>7][i&127] = WP1[i];
  for (int i=tid;i<128*64;i+=NTHR) s.wq[i>>6][i&63]  = WQ1[i];
  if (tid < 64) s.nw[tid] = w1[tid];

  l1_prefetch(s, 0, x, blockIdx.x * ROWS, tid);
  cpcommit();

  const unsigned aB = su32(&s.A[0][0]);
  const unsigned hB = su32(&s.H[0][0]);
  const unsigned pB = su32(&s.wp[0][0]);
  const unsigned qB = su32(&s.wq[0][0]);

  int buf = 0;
  for (int tile = blockIdx.x; tile < NTILES; tile += gridDim.x){
    const int n0 = tile * ROWS;
    { // issue prefetch for next tile into other buffer
      int nt = tile + gridDim.x;
      if (nt < NTILES) l1_prefetch(s, buf^1, x, nt * ROWS, tid);
      cpcommit();
    }
    cpwait1();                 // current tile's group done
    __syncthreads();
    { // ---- RMS norm from xb ----
      const int row = tid >> 4, sub = tid & 15;
      const float4* xr = reinterpret_cast<const float4*>(&s.xb[buf][row][sub*12]);
      float4 w[3];
      #pragma unroll
      for (int j=0;j<3;j++) w[j] = xr[j];
      float vv[12] = {w[0].x,w[0].y,w[0].z,w[0].w, w[1].x,w[1].y,w[1].z,w[1].w,
                      w[2].x,w[2].y,w[2].z,w[2].w};
      float sq = 0.f;
      #pragma unroll
      for (int j=0;j<12;j++) sq += vv[j]*vv[j];
      #pragma unroll
      for (int o=1;o<16;o<<=1) sq += __shfl_xor_sync(~0u, sq, o);
      float rinv = rsqrtf(sq*(1.f/64.f) + 1e-5f);
      #pragma unroll
      for (int j=0;j<12;j++){
        int c = sub*4 + j/3, m = j - 3*(j/3);
        s.A[row*3 + m][c] = __float2half(vv[j]*rinv*s.nw[c]);
      }
    }
    __syncthreads();
    // ---- GEMM1: H = A[192x64] @ wp[64x128]; 96 tiles 16x16 ----
    #pragma unroll
    for (int tt=0;tt<3;tt++){
      const int ti = warp + 32*tt;
      const int r0 = (ti>>3)<<4, c0 = (ti&7)<<4;
      float acc[2][4];
      #pragma unroll
      for (int j=0;j<2;j++){ acc[j][0]=acc[j][1]=acc[j][2]=acc[j][3]=0.f; }
      #pragma unroll
      for (int k=0;k<4;k++){
        unsigned a0,a1,a2,a3;
        ldmx4(a0,a1,a2,a3, aaddr(aB,72,r0,k*16,lane));
        unsigned b0,b1,b2,b3;
        ldmx4t(b0,b1,b2,b3, baddr(pB,136,k*16,c0,lane));
        mma16816(acc[0], a0,a1,a2,a3, b0,b1);
        mma16816(acc[1], a0,a1,a2,a3, b2,b3);
      }
      const int rr = r0 + (lane>>2), cc = c0 + ((lane&3)<<1);
      #pragma unroll
      for (int j=0;j<2;j++){
        *reinterpret_cast<__half2*>(&s.H[rr  ][cc+8*j]) = __floats2half2_rn(acc[j][0], acc[j][1]);
        *reinterpret_cast<__half2*>(&s.H[rr+8][cc+8*j]) = __floats2half2_rn(acc[j][2], acc[j][3]);
      }
    }
    __syncthreads();
    // ---- gate ----
    #pragma unroll
    for (int it=0; it<8; it++){
      int i = tid + it*NTHR;
      int n = i >> 7, o = i & 127;
      float h0 = __half2float(s.H[3*n  ][o]);
      float h1 = __half2float(s.H[3*n+1][o]);
      float h2 = __half2float(s.H[3*n+2][o]);
      float g = sigm(sqrtf(h0*h0 + h1*h1 + h2*h2 + 1e-12f));
      s.H[3*n  ][o] = __float2half(h0*g);
      s.H[3*n+1][o] = __float2half(h1*g);
      s.H[3*n+2][o] = __float2half(h2*g);
    }
    __syncthreads();
    // ---- GEMM2: 48 tiles 16x16 ----
    float acc2[2][2][4];
    #pragma unroll
    for (int tt=0;tt<2;tt++)
      #pragma unroll
      for (int j=0;j<2;j++){ acc2[tt][j][0]=acc2[tt][j][1]=acc2[tt][j][2]=acc2[tt][j][3]=0.f; }
    #pragma unroll
    for (int tt=0;tt<2;tt++){
      const int ti = warp + 32*tt;
      if (ti < 48){
        const int r0 = (ti>>2)<<4, c0 = (ti&3)<<4;
        #pragma unroll
        for (int k=0;k<8;k++){
          unsigned a0,a1,a2,a3;
          ldmx4(a0,a1,a2,a3, aaddr(hB,136,r0,k*16,lane));
          unsigned b0,b1,b2,b3;
          ldmx4t(b0,b1,b2,b3, baddr(qB,72,k*16,c0,lane));
          mma16816(acc2[tt][0], a0,a1,a2,a3, b0,b1);
          mma16816(acc2[tt][1], a0,a1,a2,a3, b2,b3);
        }
      }
    }
    __syncthreads();   // H reads done
    { // ---- residual + re-layout into ob (reuse H); raw x from xb ----
      float* ob = reinterpret_cast<float*>(&s.H[0][0]);
      #pragma unroll
      for (int tt=0;tt<2;tt++){
        const int ti = warp + 32*tt;
        if (ti < 48){
          const int r0 = (ti>>2)<<4, c0 = (ti&3)<<4;
          const int rr = r0 + (lane>>2), cc = c0 + ((lane&3)<<1);
          #pragma unroll
          for (int j=0;j<2;j++){
            int c = cc + 8*j;
            #pragma unroll
            for (int h=0;h<2;h++){
              int r = rr + 8*h;
              int n = r/3, m = r - 3*(r/3);
              ob[n*196 + c*3 + m]     = acc2[tt][j][2*h]   + s.xb[buf][n][c*3 + m];
              ob[n*196 + (c+1)*3 + m] = acc2[tt][j][2*h+1] + s.xb[buf][n][(c+1)*3 + m];
            }
          }
        }
      }
    }
    __syncthreads();
    { // ---- coalesced store ----
      const float* ob = reinterpret_cast<const float*>(&s.H[0][0]);
      #pragma unroll
      for (int i=0;i<3;i++){
        int idx = tid + i*NTHR;
        int row = idx/48, q = idx - 48*row;
        float4 v = *reinterpret_cast<const float4*>(&ob[row*196 + q*4]);
        *reinterpret_cast<float4*>(out + (size_t)(n0+row)*XDIM + 128 + q*4) = v;
      }
    }
    buf ^= 1;
  }
}

// ============================ l = 2 ============================
struct SL2 {
  float  xb[2][64][164];
  float  nw[32];
  __half wp[32][72];
  __half wq[64][40];
  __half A[320][40];
  __half H[320][72];    // reused as float[64][164] out buffer
};

DINL void l2_prefetch(SL2& s, int b, const float* x, int n0, int tid){
  #pragma unroll
  for (int i = tid; i < 2560; i += NTHR){    // 64 rows * 40 float4
    int row = i/40, q = i - 40*row;
    cpasync16(su32(&s.xb[b][row][q*4]), x + (size_t)(n0+row)*XDIM + 320 + q*4);
  }
}

__global__ __launch_bounds__(NTHR,1) void k_l2(const float* __restrict__ x,
                                               float* __restrict__ out,
                                               const float* __restrict__ w2){
  extern __shared__ __align__(16) char smem[];
  SL2& s = *reinterpret_cast<SL2*>(smem);
  const int tid = threadIdx.x, lane = tid & 31, warp = tid >> 5;

  for (int i=tid;i<32*64;i+=NTHR) s.wp[i>>6][i&63] = WP2[i];
  for (int i=tid;i<64*32;i+=NTHR) s.wq[i>>5][i&31] = WQ2[i];
  if (tid < 32) s.nw[tid] = w2[tid];

  l2_prefetch(s, 0, x, blockIdx.x * ROWS, tid);
  cpcommit();

  const unsigned aB = su32(&s.A[0][0]);
  const unsigned hB = su32(&s.H[0][0]);
  const unsigned pB = su32(&s.wp[0][0]);
  const unsigned qB = su32(&s.wq[0][0]);

  int buf = 0;
  for (int tile = blockIdx.x; tile < NTILES; tile += gridDim.x){
    const int n0 = tile * ROWS;
    {
      int nt = tile + gridDim.x;
      if (nt < NTILES) l2_prefetch(s, buf^1, x, nt * ROWS, tid);
      cpcommit();
    }
    cpwait1();
    __syncthreads();
    { // ---- RMS norm from xb ----
      const int row = tid >> 4, sub = tid & 15;
      const float2* xr = reinterpret_cast<const float2*>(&s.xb[buf][row][sub*10]);
      float2 w[5];
      #pragma unroll
      for (int j=0;j<5;j++) w[j] = xr[j];
      float vv[10] = {w[0].x,w[0].y, w[1].x,w[1].y, w[2].x,w[2].y,
                      w[3].x,w[3].y, w[4].x,w[4].y};
      float sq = 0.f;
      #pragma unroll
      for (int j=0;j<10;j++) sq += vv[j]*vv[j];
      #pragma unroll
      for (int o=1;o<16;o<<=1) sq += __shfl_xor_sync(~0u, sq, o);
      float rinv = rsqrtf(sq*(1.f/32.f) + 1e-5f);
      #pragma unroll
      for (int j=0;j<10;j++){
        int c = sub*2 + j/5, m = j - 5*(j/5);
        s.A[row*5 + m][c] = __float2half(vv[j]*rinv*s.nw[c]);
      }
    }
    __syncthreads();
    // ---- GEMM1: 80 tiles 16x16 ----
    #pragma unroll
    for (int tt=0;tt<3;tt++){
      const int ti = warp + 32*tt;
      if (ti < 80){
        const int r0 = (ti>>2)<<4, c0 = (ti&3)<<4;
        float acc[2][4];
        #pragma unroll
        for (int j=0;j<2;j++){ acc[j][0]=acc[j][1]=acc[j][2]=acc[j][3]=0.f; }
        #pragma unroll
        for (int k=0;k<2;k++){
          unsigned a0,a1,a2,a3;
          ldmx4(a0,a1,a2,a3, aaddr(aB,40,r0,k*16,lane));
          unsigned b0,b1,b2,b3;
          ldmx4t(b0,b1,b2,b3, baddr(pB,72,k*16,c0,lane));
          mma16816(acc[0], a0,a1,a2,a3, b0,b1);
          mma16816(acc[1], a0,a1,a2,a3, b2,b3);
        }
        const int rr = r0 + (lane>>2), cc = c0 + ((lane&3)<<1);
        #pragma unroll
        for (int j=0;j<2;j++){
          *reinterpret_cast<__half2*>(&s.H[rr  ][cc+8*j]) = __floats2half2_rn(acc[j][0], acc[j][1]);
          *reinterpret_cast<__half2*>(&s.H[rr+8][cc+8*j]) = __floats2half2_rn(acc[j][2], acc[j][3]);
        }
      }
    }
    __syncthreads();
    // ---- gate ----
    #pragma unroll
    for (int it=0; it<4; it++){
      int i = tid + it*NTHR;
      int n = i >> 6, o = i & 63;
      float h[5];
      #pragma unroll
      for (int m=0;m<5;m++) h[m] = __half2float(s.H[5*n+m][o]);
      float g = sigm(sqrtf(h[0]*h[0]+h[1]*h[1]+h[2]*h[2]+h[3]*h[3]+h[4]*h[4] + 1e-12f));
      #pragma unroll
      for (int m=0;m<5;m++) s.H[5*n+m][o] = __float2half(h[m]*g);
    }
    __syncthreads();
    // ---- GEMM2: 40 tiles 16x16 ----
    float acc2[2][2][4];
    #pragma unroll
    for (int tt=0;tt<2;tt++)
      #pragma unroll
      for (int j=0;j<2;j++){ acc2[tt][j][0]=acc2[tt][j][1]=acc2[tt][j][2]=acc2[tt][j][3]=0.f; }
    #pragma unroll
    for (int tt=0;tt<2;tt++){
      const int ti = warp + 32*tt;
      if (ti < 40){
        const int r0 = (ti>>1)<<4, c0 = (ti&1)<<4;
        #pragma unroll
        for (int k=0;k<4;k++){
          unsigned a0,a1,a2,a3;
          ldmx4(a0,a1,a2,a3, aaddr(hB,72,r0,k*16,lane));
          unsigned b0,b1,b2,b3;
          ldmx4t(b0,b1,b2,b3, baddr(qB,40,k*16,c0,lane));
          mma16816(acc2[tt][0], a0,a1,a2,a3, b0,b1);
          mma16816(acc2[tt][1], a0,a1,a2,a3, b2,b3);
        }
      }
    }
    __syncthreads();   // H reads done
    { // ---- residual + re-layout; raw x from xb ----
      float* ob = reinterpret_cast<float*>(&s.H[0][0]);
      #pragma unroll
      for (int tt=0;tt<2;tt++){
        const int ti = warp + 32*tt;
        if (ti < 40){
          const int r0 = (ti>>1)<<4, c0 = (ti&1)<<4;
          const int rr = r0 + (lane>>2), cc = c0 + ((lane&3)<<1);
          #pragma unroll
          for (int j=0;j<2;j++){
            int c = cc + 8*j;
            #pragma unroll
            for (int h=0;h<2;h++){
              int r = rr + 8*h;
              int n = r/5, m = r - 5*(r/5);
              ob[n*164 + c*5 + m]     = acc2[tt][j][2*h]   + s.xb[buf][n][c*5 + m];
              ob[n*164 + (c+1)*5 + m] = acc2[tt][j][2*h+1] + s.xb[buf][n][(c+1)*5 + m];
            }
          }
        }
      }
    }
    __syncthreads();
    { // ---- coalesced store ----
      const float* ob = reinterpret_cast<const float*>(&s.H[0][0]);
      #pragma unroll
      for (int i=0;i<3;i++){
        int idx = tid + i*NTHR;
        if (idx < 2560){
          int row = idx/40, q = idx - 40*row;
          float4 v = *reinterpret_cast<const float4*>(&ob[row*164 + q*4]);
          *reinterpret_cast<float4*>(out + (size_t)(n0+row)*XDIM + 320 + q*4) = v;
        }
      }
    }
    buf ^= 1;
  }
}

extern "C" void kernel_launch(void* const* d_in, const int* in_sizes, int n_in,
                              void* d_out, int out_size){
  const float* x   = (const float*)d_in[0];
  const float* nw0 = (const float*)d_in[1];
  const float* nb0 = (const float*)d_in[2];
  const float* nw1 = (const float*)d_in[3];
  const float* nw2 = (const float*)d_in[4];
  const float* p0  = (const float*)d_in[5];
  const float* p1  = (const float*)d_in[6];
  const float* p2  = (const float*)d_in[7];
  const float* q0  = (const float*)d_in[8];
  const float* q1  = (const float*)d_in[9];
  const float* q2  = (const float*)d_in[10];
  float* out = (float*)d_out;

  cudaFuncSetAttribute(k_l0, cudaFuncAttributeMaxDynamicSharedMemorySize, (int)sizeof(SL0));
  cudaFuncSetAttribute(k_l1, cudaFuncAttributeMaxDynamicSharedMemorySize, (int)sizeof(SL1));
  cudaFuncSetAttribute(k_l2, cudaFuncAttributeMaxDynamicSharedMemorySize, (int)sizeof(SL2));

  k_prep<<<96, 256>>>(p0, p1, p2, q0, q1, q2);
  k_l0<<<GRID, NTHR, sizeof(SL0)>>>(x, out, nw0, nb0);
  k_l1<<<GRID, NTHR, sizeof(SL1)>>>(x, out, nw1);
  k_l2<<<GRID, NTHR, sizeof(SL2)>>>(x, out, nw2);
}

// round 5
// speedup vs baseline: 1.2919x; 1.1316x over previous
#include <cuda_runtime.h>
#include <cuda_fp16.h>
#include <cstdint>

#define NROW 200000
#define XDIM 480
#define ROWS 64
#define NTILES (NROW / ROWS)   // 3125 exactly
#define GRID 152
#define NTHR 1024

#define DINL __device__ __forceinline__

DINL unsigned su32(const void* p){ return (unsigned)__cvta_generic_to_shared(p); }

DINL void cpasync16(unsigned dst, const void* src){
  asm volatile("cp.async.ca.shared.global [%0], [%1], 16;" :: "r"(dst), "l"(src));
}
DINL void cpcommit(){ asm volatile("cp.async.commit_group;" ::: "memory"); }
DINL void cpwait0(){ asm volatile("cp.async.wait_group 0;" ::: "memory"); }

DINL void ldmx4(unsigned &r0,unsigned &r1,unsigned &r2,unsigned &r3, unsigned a){
  asm volatile("ldmatrix.sync.aligned.m8n8.x4.shared.b16 {%0,%1,%2,%3}, [%4];"
    : "=r"(r0),"=r"(r1),"=r"(r2),"=r"(r3) : "r"(a));
}
DINL void ldmx4t(unsigned &r0,unsigned &r1,unsigned &r2,unsigned &r3, unsigned a){
  asm volatile("ldmatrix.sync.aligned.m8n8.x4.trans.shared.b16 {%0,%1,%2,%3}, [%4];"
    : "=r"(r0),"=r"(r1),"=r"(r2),"=r"(r3) : "r"(a));
}
DINL void ldmx2t(unsigned &r0,unsigned &r1, unsigned a){
  asm volatile("ldmatrix.sync.aligned.m8n8.x2.trans.shared.b16 {%0,%1}, [%2];"
    : "=r"(r0),"=r"(r1) : "r"(a));
}
DINL void mma16816(float* c, unsigned a0,unsigned a1,unsigned a2,unsigned a3,
                   unsigned b0,unsigned b1){
  asm volatile("mma.sync.aligned.m16n8k16.row.col.f32.f16.f16.f32 "
    "{%0,%1,%2,%3}, {%4,%5,%6,%7}, {%8,%9}, {%0,%1,%2,%3};"
    : "+f"(c[0]),"+f"(c[1]),"+f"(c[2]),"+f"(c[3])
    : "r"(a0),"r"(a1),"r"(a2),"r"(a3),"r"(b0),"r"(b1));
}
DINL float sigm(float v){ return 1.f/(1.f+__expf(-v)); }

DINL unsigned aaddr(unsigned base, int stride, int r0, int k0, int lane){
  int r = r0 + (lane & 15);
  int c = k0 + ((lane >> 4) << 3);
  return base + (unsigned)((r * stride + c) << 1);
}
DINL unsigned baddr(unsigned base, int stride, int k0, int c0, int lane){
  int r = k0 + (lane & 7) + (((lane >> 3) & 1) << 3);
  int c = c0 + ((lane >> 4) << 3);
  return base + (unsigned)((r * stride + c) << 1);
}
// x2.trans address: rows k0..k0+15 of col group c0 (8 wide)
DINL unsigned b2addr(unsigned base, int stride, int k0, int c0, int lane){
  int r = k0 + (lane & 15);
  return base + (unsigned)((r * stride + c0) << 1);
}

// fp16 weights with 1/sqrt(fan_in) folded
__device__ __half WP0[128*256];
__device__ __half WQ0[256*128];
__device__ __half WP1[64*128];
__device__ __half WQ1[128*64];
__device__ __half WP2[32*64];
__device__ __half WQ2[64*32];

__global__ void k_prep(const float* __restrict__ p0, const float* __restrict__ p1,
                       const float* __restrict__ p2, const float* __restrict__ q0,
                       const float* __restrict__ q1, const float* __restrict__ q2){
  int t = blockIdx.x*blockDim.x + threadIdx.x, st = gridDim.x*blockDim.x;
  for (int i=t;i<128*256;i+=st) WP0[i] = __float2half(p0[i]*0.08838834764831845f);
  for (int i=t;i<64*128;i+=st)  WP1[i] = __float2half(p1[i]*0.125f);
  for (int i=t;i<32*64;i+=st)   WP2[i] = __float2half(p2[i]*0.17677669529663687f);
  for (int i=t;i<256*128;i+=st) WQ0[i] = __float2half(q0[i]*0.0625f);
  for (int i=t;i<128*64;i+=st)  WQ1[i] = __float2half(q1[i]*0.08838834764831845f);
  for (int i=t;i<64*32;i+=st)   WQ2[i] = __float2half(q2[i]*0.125f);
}

// ============================ l = 0 ============================
struct SL0 {
  float  nw[128], nb[128];
  __half wp[128][264];
  __half wq[256][136];
  __half A[64][136];
  __half H[64][264];
  float  xb[64][132];
};

DINL void l0_prefetch(SL0& s, const float* x, int n0, int tid){
  for (int i = tid; i < 2048; i += NTHR){
    int row = i >> 5, q = i & 31;
    cpasync16(su32(&s.xb[row][q*4]), x + (size_t)(n0+row)*XDIM + q*4);
  }
}

__global__ __launch_bounds__(NTHR,1) void k_l0(const float* __restrict__ x,
                                               float* __restrict__ out,
                                               const float* __restrict__ w0,
                                               const float* __restrict__ b0){
  extern __shared__ __align__(16) char smem[];
  SL0& s = *reinterpret_cast<SL0*>(smem);
  const int tid = threadIdx.x, lane = tid & 31, warp = tid >> 5;

  for (int i=tid;i<128*256;i+=NTHR) s.wp[i>>8][i&255] = WP0[i];
  for (int i=tid;i<256*128;i+=NTHR) s.wq[i>>7][i&127] = WQ0[i];
  if (tid < 128){ s.nw[tid] = w0[tid]; s.nb[tid] = b0[tid]; }

  l0_prefetch(s, x, blockIdx.x * ROWS, tid);
  cpcommit();

  const unsigned aB = su32(&s.A[0][0]);
  const unsigned hB = su32(&s.H[0][0]);
  const unsigned pB = su32(&s.wp[0][0]);
  const unsigned qB = su32(&s.wq[0][0]);

  const int r0  = (warp >> 3) << 4;
  const int c0  = (warp & 7) << 5;
  const int c0b = (warp & 7) << 4;

  for (int tile = blockIdx.x; tile < NTILES; tile += gridDim.x){
    const int n0 = tile * ROWS;
    cpwait0();
    __syncthreads();
    { // ---- norm from xb ----
      const int row = tid >> 4, sub = tid & 15;
      float4 v0 = *reinterpret_cast<const float4*>(&s.xb[row][sub*8]);
      float4 v1 = *reinterpret_cast<const float4*>(&s.xb[row][sub*8+4]);
      float vv[8] = {v0.x,v0.y,v0.z,v0.w, v1.x,v1.y,v1.z,v1.w};
      float sm = 0.f, sq = 0.f;
      #pragma unroll
      for (int j=0;j<8;j++){ sm += vv[j]; sq += vv[j]*vv[j]; }
      #pragma unroll
      for (int o=1;o<16;o<<=1){ sm += __shfl_xor_sync(~0u, sm, o); sq += __shfl_xor_sync(~0u, sq, o); }
      float mu = sm * (1.f/128.f);
      float rinv = rsqrtf(sq*(1.f/128.f) - mu*mu + 1e-5f);
      const int cb = sub*8;
      __half2 h[4];
      #pragma unroll
      for (int j=0;j<4;j++){
        float a0f = (vv[2*j]   - mu)*rinv*s.nw[cb+2*j]   + s.nb[cb+2*j];
        float a1f = (vv[2*j+1] - mu)*rinv*s.nw[cb+2*j+1] + s.nb[cb+2*j+1];
        h[j] = __floats2half2_rn(a0f, a1f);
      }
      *reinterpret_cast<uint4*>(&s.A[row][cb]) = *reinterpret_cast<uint4*>(h);
    }
    __syncthreads();
    { // prefetch next tile while GEMMs run
      int nt = tile + gridDim.x;
      if (nt < NTILES) l0_prefetch(s, x, nt * ROWS, tid);
      cpcommit();
    }
    { // ---- GEMM1 + sigmoid -> H ----
      float acc[4][4];
      #pragma unroll
      for (int j=0;j<4;j++){ acc[j][0]=acc[j][1]=acc[j][2]=acc[j][3]=0.f; }
      #pragma unroll
      for (int k=0;k<8;k++){
        unsigned a0,a1,a2,a3;
        ldmx4(a0,a1,a2,a3, aaddr(aB,136,r0,k*16,lane));
        #pragma unroll
        for (int j=0;j<2;j++){
          unsigned b0,b1,b2,b3;
          ldmx4t(b0,b1,b2,b3, baddr(pB,264,k*16,c0+j*16,lane));
          mma16816(acc[2*j],   a0,a1,a2,a3, b0,b1);
          mma16816(acc[2*j+1], a0,a1,a2,a3, b2,b3);
        }
      }
      const int rr = r0 + (lane>>2), cc = c0 + ((lane&3)<<1);
      #pragma unroll
      for (int j=0;j<4;j++){
        *reinterpret_cast<__half2*>(&s.H[rr  ][cc+8*j]) = __floats2half2_rn(sigm(acc[j][0]), sigm(acc[j][1]));
        *reinterpret_cast<__half2*>(&s.H[rr+8][cc+8*j]) = __floats2half2_rn(sigm(acc[j][2]), sigm(acc[j][3]));
      }
    }
    __syncthreads();
    { // ---- GEMM2 + direct residual epilogue ----
      float acc2[2][4];
      #pragma unroll
      for (int j=0;j<2;j++){ acc2[j][0]=acc2[j][1]=acc2[j][2]=acc2[j][3]=0.f; }
      #pragma unroll
      for (int k=0;k<16;k++){
        unsigned a0,a1,a2,a3;
        ldmx4(a0,a1,a2,a3, aaddr(hB,264,r0,k*16,lane));
        unsigned b0,b1,b2,b3;
        ldmx4t(b0,b1,b2,b3, baddr(qB,136,k*16,c0b,lane));
        mma16816(acc2[0], a0,a1,a2,a3, b0,b1);
        mma16816(acc2[1], a0,a1,a2,a3, b2,b3);
      }
      const int rr = r0 + (lane>>2), cc = c0b + ((lane&3)<<1);
      #pragma unroll
      for (int j=0;j<2;j++){
        int c = cc + 8*j;
        size_t i0 = (size_t)(n0+rr)*XDIM + c;
        size_t i1 = (size_t)(n0+rr+8)*XDIM + c;
        float2 xv0 = *reinterpret_cast<const float2*>(x + i0);
        float2 xv1 = *reinterpret_cast<const float2*>(x + i1);
        *reinterpret_cast<float2*>(out + i0) = make_float2(acc2[j][0]+xv0.x, acc2[j][1]+xv0.y);
        *reinterpret_cast<float2*>(out + i1) = make_float2(acc2[j][2]+xv1.x, acc2[j][3]+xv1.y);
      }
    }
  }
}

// ============================ l = 1 ============================
struct SL1 {
  float  nw[64];
  float  xb[64][196];        // staged x slice (192 data + pad)
  __half wp[64][136];
  __half wq[128][72];
  __half A[3][64][72];       // per-m A matrices
  __half H[192][136];        // gated hidden, rows n*3+m; reused as float ob[64][196]
};

DINL void l1_prefetch(SL1& s, const float* x, int n0, int tid){
  for (int i = tid; i < 3072; i += NTHR){    // 64 rows * 48 float4
    int row = i/48, q = i - 48*row;
    cpasync16(su32(&s.xb[row][q*4]), x + (size_t)(n0+row)*XDIM + 128 + q*4);
  }
}

__global__ __launch_bounds__(NTHR,1) void k_l1(const float* __restrict__ x,
                                               float* __restrict__ out,
                                               const float* __restrict__ w1){
  extern __shared__ __align__(16) char smem[];
  SL1& s = *reinterpret_cast<SL1*>(smem);
  const int tid = threadIdx.x, lane = tid & 31, warp = tid >> 5;

  for (int i=tid;i<64*128;i+=NTHR) s.wp[i>>7][i&127] = WP1[i];
  for (int i=tid;i<128*64;i+=NTHR) s.wq[i>>6][i&63]  = WQ1[i];
  if (tid < 64) s.nw[tid] = w1[tid];

  l1_prefetch(s, x, blockIdx.x * ROWS, tid);
  cpcommit();

  const unsigned aB = su32(&s.A[0][0][0]);
  const unsigned hB = su32(&s.H[0][0]);
  const unsigned pB = su32(&s.wp[0][0]);
  const unsigned qB = su32(&s.wq[0][0]);

  // GEMM1 task: 4 rt x 8 ct (16-wide), all 3 m per warp
  const int g1r = (warp >> 3) << 4;
  const int g1c = (warp & 7) << 4;

  for (int tile = blockIdx.x; tile < NTILES; tile += gridDim.x){
    const int n0 = tile * ROWS;
    cpwait0();
    __syncthreads();
    { // ---- RMS norm from xb -> A[m][n][c] ----
      const int row = tid >> 4, sub = tid & 15;
      const float4* xr = reinterpret_cast<const float4*>(&s.xb[row][sub*12]);
      float4 w[3];
      #pragma unroll
      for (int j=0;j<3;j++) w[j] = xr[j];
      float vv[12] = {w[0].x,w[0].y,w[0].z,w[0].w, w[1].x,w[1].y,w[1].z,w[1].w,
                      w[2].x,w[2].y,w[2].z,w[2].w};
      float sq = 0.f;
      #pragma unroll
      for (int j=0;j<12;j++) sq += vv[j]*vv[j];
      #pragma unroll
      for (int o=1;o<16;o<<=1) sq += __shfl_xor_sync(~0u, sq, o);
      float rinv = rsqrtf(sq*(1.f/64.f) + 1e-5f);
      #pragma unroll
      for (int j=0;j<12;j++){
        int c = sub*4 + j/3, m = j - 3*(j/3);
        s.A[m][row][c] = __float2half(vv[j]*rinv*s.nw[c]);
      }
    }
    __syncthreads();
    { // prefetch next tile (xb consumed) — overlaps GEMMs
      int nt = tile + gridDim.x;
      if (nt < NTILES) l1_prefetch(s, x, nt * ROWS, tid);
      cpcommit();
    }
    { // ---- GEMM1 (m-batched) + in-register gate -> H[n*3+m][o] ----
      float acc[3][2][4];
      #pragma unroll
      for (int m=0;m<3;m++)
        #pragma unroll
        for (int j=0;j<2;j++){ acc[m][j][0]=acc[m][j][1]=acc[m][j][2]=acc[m][j][3]=0.f; }
      #pragma unroll
      for (int k=0;k<4;k++){
        unsigned b0,b1,b2,b3;
        ldmx4t(b0,b1,b2,b3, baddr(pB,136,k*16,g1c,lane));
        #pragma unroll
        for (int m=0;m<3;m++){
          unsigned a0,a1,a2,a3;
          ldmx4(a0,a1,a2,a3, aaddr(aB + m*9216u, 72, g1r, k*16, lane));
          mma16816(acc[m][0], a0,a1,a2,a3, b0,b1);
          mma16816(acc[m][1], a0,a1,a2,a3, b2,b3);
        }
      }
      const int rr = g1r + (lane>>2), ccl = (lane&3)<<1;
      #pragma unroll
      for (int j=0;j<2;j++){
        float g0 = sigm(sqrtf(acc[0][j][0]*acc[0][j][0] + acc[1][j][0]*acc[1][j][0] + acc[2][j][0]*acc[2][j][0] + 1e-12f));
        float g1 = sigm(sqrtf(acc[0][j][1]*acc[0][j][1] + acc[1][j][1]*acc[1][j][1] + acc[2][j][1]*acc[2][j][1] + 1e-12f));
        float g2 = sigm(sqrtf(acc[0][j][2]*acc[0][j][2] + acc[1][j][2]*acc[1][j][2] + acc[2][j][2]*acc[2][j][2] + 1e-12f));
        float g3 = sigm(sqrtf(acc[0][j][3]*acc[0][j][3] + acc[1][j][3]*acc[1][j][3] + acc[2][j][3]*acc[2][j][3] + 1e-12f));
        int c = g1c + 8*j + ccl;
        #pragma unroll
        for (int m=0;m<3;m++){
          *reinterpret_cast<__half2*>(&s.H[3*rr+m][c])     = __floats2half2_rn(acc[m][j][0]*g0, acc[m][j][1]*g1);
          *reinterpret_cast<__half2*>(&s.H[3*(rr+8)+m][c]) = __floats2half2_rn(acc[m][j][2]*g2, acc[m][j][3]*g3);
        }
      }
    }
    __syncthreads();
    // ---- GEMM2: Y = H[192x128] @ wq[128x64]; 48 tiles 16x16 ----
    float acc2[2][2][4];
    #pragma unroll
    for (int tt=0;tt<2;tt++)
      #pragma unroll
      for (int j=0;j<2;j++){ acc2[tt][j][0]=acc2[tt][j][1]=acc2[tt][j][2]=acc2[tt][j][3]=0.f; }
    #pragma unroll
    for (int tt=0;tt<2;tt++){
      const int ti = warp + 32*tt;
      if (ti < 48){
        const int r0 = (ti>>2)<<4, c0 = (ti&3)<<4;
        #pragma unroll
        for (int k=0;k<8;k++){
          unsigned a0,a1,a2,a3;
          ldmx4(a0,a1,a2,a3, aaddr(hB,136,r0,k*16,lane));
          unsigned b0,b1,b2,b3;
          ldmx4t(b0,b1,b2,b3, baddr(qB,72,k*16,c0,lane));
          mma16816(acc2[tt][0], a0,a1,a2,a3, b0,b1);
          mma16816(acc2[tt][1], a0,a1,a2,a3, b2,b3);
        }
      }
    }
    __syncthreads();   // H reads done
    { // ---- re-layout (n*3+m, c) -> (n, c*3+m) into ob (reuse H) ----
      float* ob = reinterpret_cast<float*>(&s.H[0][0]);
      #pragma unroll
      for (int tt=0;tt<2;tt++){
        const int ti = warp + 32*tt;
        if (ti < 48){
          const int r0 = (ti>>2)<<4, c0 = (ti&3)<<4;
          const int rr = r0 + (lane>>2), cc = c0 + ((lane&3)<<1);
          #pragma unroll
          for (int j=0;j<2;j++){
            int c = cc + 8*j;
            #pragma unroll
            for (int h=0;h<2;h++){
              int r = rr + 8*h;
              int n = r/3, m = r - 3*(r/3);
              ob[n*196 + c*3 + m]     = acc2[tt][j][2*h];
              ob[n*196 + (c+1)*3 + m] = acc2[tt][j][2*h+1];
            }
          }
        }
      }
    }
    __syncthreads();
    { // ---- coalesced store + residual (x re-read, L2 hit) ----
      const float* ob = reinterpret_cast<const float*>(&s.H[0][0]);
      #pragma unroll
      for (int i=0;i<3;i++){
        int idx = tid + i*NTHR;
        int row = idx/48, q = idx - 48*row;
        float4 v = *reinterpret_cast<const float4*>(&ob[row*196 + q*4]);
        const float4 xv = *reinterpret_cast<const float4*>(x + (size_t)(n0+row)*XDIM + 128 + q*4);
        *reinterpret_cast<float4*>(out + (size_t)(n0+row)*XDIM + 128 + q*4) =
          make_float4(v.x+xv.x, v.y+xv.y, v.z+xv.z, v.w+xv.w);
      }
    }
  }
}

// ============================ l = 2 ============================
struct SL2 {
  float  nw[32];
  float  xb[64][164];        // staged x slice (160 data + pad)
  __half wp[32][72];
  __half wq[64][40];
  __half A[5][64][40];       // per-m A matrices
  __half H[320][72];         // gated hidden, rows n*5+m; reused as float ob[64][164]
};

DINL void l2_prefetch(SL2& s, const float* x, int n0, int tid){
  for (int i = tid; i < 2560; i += NTHR){    // 64 rows * 40 float4
    int row = i/40, q = i - 40*row;
    cpasync16(su32(&s.xb[row][q*4]), x + (size_t)(n0+row)*XDIM + 320 + q*4);
  }
}

__global__ __launch_bounds__(NTHR,1) void k_l2(const float* __restrict__ x,
                                               float* __restrict__ out,
                                               const float* __restrict__ w2){
  extern __shared__ __align__(16) char smem[];
  SL2& s = *reinterpret_cast<SL2*>(smem);
  const int tid = threadIdx.x, lane = tid & 31, warp = tid >> 5;

  for (int i=tid;i<32*64;i+=NTHR) s.wp[i>>6][i&63] = WP2[i];
  for (int i=tid;i<64*32;i+=NTHR) s.wq[i>>5][i&31] = WQ2[i];
  if (tid < 32) s.nw[tid] = w2[tid];

  l2_prefetch(s, x, blockIdx.x * ROWS, tid);
  cpcommit();

  const unsigned aB = su32(&s.A[0][0][0]);
  const unsigned hB = su32(&s.H[0][0]);
  const unsigned pB = su32(&s.wp[0][0]);
  const unsigned qB = su32(&s.wq[0][0]);

  // GEMM1 task: 4 rt x 8 ct (8-wide), all 5 m per warp
  const int g1r = (warp >> 3) << 4;
  const int g1c = (warp & 7) << 3;

  for (int tile = blockIdx.x; tile < NTILES; tile += gridDim.x){
    const int n0 = tile * ROWS;
    cpwait0();
    __syncthreads();
    { // ---- RMS norm from xb -> A[m][n][c] ----
      const int row = tid >> 4, sub = tid & 15;
      const float2* xr = reinterpret_cast<const float2*>(&s.xb[row][sub*10]);
      float2 w[5];
      #pragma unroll
      for (int j=0;j<5;j++) w[j] = xr[j];
      float vv[10] = {w[0].x,w[0].y, w[1].x,w[1].y, w[2].x,w[2].y,
                      w[3].x,w[3].y, w[4].x,w[4].y};
      float sq = 0.f;
      #pragma unroll
      for (int j=0;j<10;j++) sq += vv[j]*vv[j];
      #pragma unroll
      for (int o=1;o<16;o<<=1) sq += __shfl_xor_sync(~0u, sq, o);
      float rinv = rsqrtf(sq*(1.f/32.f) + 1e-5f);
      #pragma unroll
      for (int j=0;j<10;j++){
        int c = sub*2 + j/5, m = j - 5*(j/5);
        s.A[m][row][c] = __float2half(vv[j]*rinv*s.nw[c]);
      }
    }
    __syncthreads();
    { // prefetch next tile
      int nt = tile + gridDim.x;
      if (nt < NTILES) l2_prefetch(s, x, nt * ROWS, tid);
      cpcommit();
    }
    { // ---- GEMM1 (m-batched, 16x8 tiles) + in-register gate -> H[n*5+m][o] ----
      float acc[5][4];
      #pragma unroll
      for (int m=0;m<5;m++){ acc[m][0]=acc[m][1]=acc[m][2]=acc[m][3]=0.f; }
      #pragma unroll
      for (int k=0;k<2;k++){
        unsigned b0,b1;
        ldmx2t(b0,b1, b2addr(pB,72,k*16,g1c,lane));
        #pragma unroll
        for (int m=0;m<5;m++){
          unsigned a0,a1,a2,a3;
          ldmx4(a0,a1,a2,a3, aaddr(aB + m*5120u, 40, g1r, k*16, lane));
          mma16816(acc[m], a0,a1,a2,a3, b0,b1);
        }
      }
      const int rr = g1r + (lane>>2);
      const int c  = g1c + ((lane&3)<<1);
      float g0 = sigm(sqrtf(acc[0][0]*acc[0][0]+acc[1][0]*acc[1][0]+acc[2][0]*acc[2][0]+acc[3][0]*acc[3][0]+acc[4][0]*acc[4][0] + 1e-12f));
      float g1 = sigm(sqrtf(acc[0][1]*acc[0][1]+acc[1][1]*acc[1][1]+acc[2][1]*acc[2][1]+acc[3][1]*acc[3][1]+acc[4][1]*acc[4][1] + 1e-12f));
      float g2 = sigm(sqrtf(acc[0][2]*acc[0][2]+acc[1][2]*acc[1][2]+acc[2][2]*acc[2][2]+acc[3][2]*acc[3][2]+acc[4][2]*acc[4][2] + 1e-12f));
      float g3 = sigm(sqrtf(acc[0][3]*acc[0][3]+acc[1][3]*acc[1][3]+acc[2][3]*acc[2][3]+acc[3][3]*acc[3][3]+acc[4][3]*acc[4][3] + 1e-12f));
      #pragma unroll
      for (int m=0;m<5;m++){
        *reinterpret_cast<__half2*>(&s.H[5*rr+m][c])     = __floats2half2_rn(acc[m][0]*g0, acc[m][1]*g1);
        *reinterpret_cast<__half2*>(&s.H[5*(rr+8)+m][c]) = __floats2half2_rn(acc[m][2]*g2, acc[m][3]*g3);
      }
    }
    __syncthreads();
    // ---- GEMM2: Y = H[320x64] @ wq[64x32]; 40 tiles 16x16 ----
    float acc2[2][2][4];
    #pragma unroll
    for (int tt=0;tt<2;tt++)
      #pragma unroll
      for (int j=0;j<2;j++){ acc2[tt][j][0]=acc2[tt][j][1]=acc2[tt][j][2]=acc2[tt][j][3]=0.f; }
    #pragma unroll
    for (int tt=0;tt<2;tt++){
      const int ti = warp + 32*tt;
      if (ti < 40){
        const int r0 = (ti>>1)<<4, c0 = (ti&1)<<4;
        #pragma unroll
        for (int k=0;k<4;k++){
          unsigned a0,a1,a2,a3;
          ldmx4(a0,a1,a2,a3, aaddr(hB,72,r0,k*16,lane));
          unsigned b0,b1,b2,b3;
          ldmx4t(b0,b1,b2,b3, baddr(qB,40,k*16,c0,lane));
          mma16816(acc2[tt][0], a0,a1,a2,a3, b0,b1);
          mma16816(acc2[tt][1], a0,a1,a2,a3, b2,b3);
        }
      }
    }
    __syncthreads();   // H reads done
    { // ---- re-layout (n*5+m, c) -> (n, c*5+m) into ob ----
      float* ob = reinterpret_cast<float*>(&s.H[0][0]);
      #pragma unroll
      for (int tt=0;tt<2;tt++){
        const int ti = warp + 32*tt;
        if (ti < 40){
          const int r0 = (ti>>1)<<4, c0 = (ti&1)<<4;
          const int rr = r0 + (lane>>2), cc = c0 + ((lane&3)<<1);
          #pragma unroll
          for (int j=0;j<2;j++){
            int c = cc + 8*j;
            #pragma unroll
            for (int h=0;h<2;h++){
              int r = rr + 8*h;
              int n = r/5, m = r - 5*(r/5);
              ob[n*164 + c*5 + m]     = acc2[tt][j][2*h];
              ob[n*164 + (c+1)*5 + m] = acc2[tt][j][2*h+1];
            }
          }
        }
      }
    }
    __syncthreads();
    { // ---- coalesced store + residual (x re-read, L2 hit) ----
      const float* ob = reinterpret_cast<const float*>(&s.H[0][0]);
      #pragma unroll
      for (int i=0;i<3;i++){
        int idx = tid + i*NTHR;
        if (idx < 2560){
          int row = idx/40, q = idx - 40*row;
          float4 v = *reinterpret_cast<const float4*>(&ob[row*164 + q*4]);
          const float4 xv = *reinterpret_cast<const float4*>(x + (size_t)(n0+row)*XDIM + 320 + q*4);
          *reinterpret_cast<float4*>(out + (size_t)(n0+row)*XDIM + 320 + q*4) =
            make_float4(v.x+xv.x, v.y+xv.y, v.z+xv.z, v.w+xv.w);
        }
      }
    }
  }
}

extern "C" void kernel_launch(void* const* d_in, const int* in_sizes, int n_in,
                              void* d_out, int out_size){
  const float* x   = (const float*)d_in[0];
  const float* nw0 = (const float*)d_in[1];
  const float* nb0 = (const float*)d_in[2];
  const float* nw1 = (const float*)d_in[3];
  const float* nw2 = (const float*)d_in[4];
  const float* p0  = (const float*)d_in[5];
  const float* p1  = (const float*)d_in[6];
  const float* p2  = (const float*)d_in[7];
  const float* q0  = (const float*)d_in[8];
  const float* q1  = (const float*)d_in[9];
  const float* q2  = (const float*)d_in[10];
  float* out = (float*)d_out;

  cudaFuncSetAttribute(k_l0, cudaFuncAttributeMaxDynamicSharedMemorySize, (int)sizeof(SL0));
  cudaFuncSetAttribute(k_l1, cudaFuncAttributeMaxDynamicSharedMemorySize, (int)sizeof(SL1));
  cudaFuncSetAttribute(k_l2, cudaFuncAttributeMaxDynamicSharedMemorySize, (int)sizeof(SL2));

  k_prep<<<96, 256>>>(p0, p1, p2, q0, q1, q2);
  k_l0<<<GRID, NTHR, sizeof(SL0)>>>(x, out, nw0, nb0);
  k_l1<<<GRID, NTHR, sizeof(SL1)>>>(x, out, nw1);
  k_l2<<<GRID, NTHR, sizeof(SL2)>>>(x, out, nw2);
}